// round 13
// baseline (speedup 1.0000x reference)
#include <cuda_runtime.h>
#include <cuda_bf16.h>
#include <cstdint>

#define NF    8192
#define NROWS 16384
#define EDIM  4096

__device__ float g_emb[NROWS * 64];
__device__ float g_X[2 * NF * 256];
__device__ float g_H1[512 * 16 * 64];
__device__ float g_C1[512 * 16 * 64];
__device__ float g_H2[512 * 16 * 32];
__device__ float g_C2[512 * 16 * 32];
__device__ __nv_bfloat16 gA1h[(size_t)NROWS * 96];
__device__ __nv_bfloat16 gA1l[(size_t)NROWS * 96];
__device__ __nv_bfloat16 gW1h[(size_t)EDIM * 96];
__device__ __nv_bfloat16 gW1l[(size_t)EDIM * 96];
__device__ __nv_bfloat16 gB2h[64 * EDIM];
__device__ __nv_bfloat16 gB2l[64 * EDIM];

__device__ __forceinline__ uint32_t smem_to_u32(const void* p) {
    uint32_t a;
    asm("{ .reg .u64 t; cvta.to.shared.u64 t, %1; cvt.u32.u64 %0, t; }" : "=r"(a) : "l"(p));
    return a;
}
__device__ __forceinline__ void ldsm4(uint32_t* r, uint32_t addr) {
    asm volatile("ldmatrix.sync.aligned.m8n8.x4.shared.b16 {%0,%1,%2,%3}, [%4];"
                 : "=r"(r[0]), "=r"(r[1]), "=r"(r[2]), "=r"(r[3]) : "r"(addr));
}
__device__ __forceinline__ void mma_bf16(float* d, const uint32_t* a, const uint32_t* b) {
    asm volatile("mma.sync.aligned.m16n8k16.row.col.f32.bf16.bf16.f32 "
                 "{%0,%1,%2,%3}, {%4,%5,%6,%7}, {%8,%9}, {%0,%1,%2,%3};"
                 : "+f"(d[0]), "+f"(d[1]), "+f"(d[2]), "+f"(d[3])
                 : "r"(a[0]), "r"(a[1]), "r"(a[2]), "r"(a[3]), "r"(b[0]), "r"(b[1]));
}
__device__ __forceinline__ void cp_async16(uint32_t saddr, const void* g) {
    asm volatile("cp.async.cg.shared.global [%0], [%1], 16;" :: "r"(saddr), "l"(g));
}
#define CP_COMMIT() asm volatile("cp.async.commit_group;" ::: "memory")
#define CP_WAIT0()  asm volatile("cp.async.wait_group 0;" ::: "memory")
__device__ __forceinline__ unsigned long long ffma2(unsigned long long a, unsigned long long b, unsigned long long c) {
    unsigned long long d;
    asm("fma.rn.f32x2 %0, %1, %2, %3;" : "=l"(d) : "l"(a), "l"(b), "l"(c));
    return d;
}
__device__ __forceinline__ unsigned long long pack2(float x) {
    unsigned long long d;
    unsigned int u = __float_as_uint(x);
    asm("mov.b64 %0, {%1, %1};" : "=l"(d) : "r"(u));
    return d;
}
__device__ __forceinline__ void unpack2(unsigned long long v, float& lo, float& hi) {
    unsigned int a, b;
    asm("mov.b64 {%0, %1}, %2;" : "=r"(a), "=r"(b) : "l"(v));
    lo = __uint_as_float(a);
    hi = __uint_as_float(b);
}
__device__ __forceinline__ float sigf(float x) { return 1.0f / (1.0f + __expf(-x)); }
__device__ __forceinline__ float tanh_f(float x) { return 1.0f - 2.0f / (__expf(2.0f * x) + 1.0f); }
__device__ __forceinline__ void split_bf16(float x, __nv_bfloat16& h, __nv_bfloat16& l) {
    h = __float2bfloat16(x);
    l = __float2bfloat16(x - __bfloat162float(h));
}
__device__ __forceinline__ uint32_t packbf(float a, float b) {
    __nv_bfloat16 x = __float2bfloat16(a), y = __float2bfloat16(b);
    return (uint32_t)__bfloat16_as_ushort(y) << 16 | __bfloat16_as_ushort(x);
}

// ============== k_spp (emits gA1 hi/lo split directly) ==============
__global__ __launch_bounds__(256) void k_spp(const float* __restrict__ frames,
                                             const float* __restrict__ Wf,
                                             const float* __restrict__ bf,
                                             float* __restrict__ out_pooled,
                                             float* __restrict__ out_fpooled) {
    __shared__ float sF[3 * 48 * 48];
    __shared__ float sL4[48];
    __shared__ float sP[90];
    const int n = blockIdx.x, t = threadIdx.x;
    const float4* src = reinterpret_cast<const float4*>(frames + (size_t)n * 6912);
    float4* dst = reinterpret_cast<float4*>(sF);
    #pragma unroll
    for (int i = t; i < 1728; i += 256) dst[i] = src[i];
    __syncthreads();
    {
        int og = t >> 2, sub = t & 3;
        bool act = (og < 48);
        float m = -1e30f;
        if (act) {
            int c = og >> 4, rem = og & 15, i = rem >> 2, j = rem & 3;
            const float* base = sF + c * 2304 + (i * 12 + sub * 3) * 48 + j * 12;
            #pragma unroll
            for (int r = 0; r < 3; r++)
                #pragma unroll
                for (int q = 0; q < 12; q++) m = fmaxf(m, base[r * 48 + q]);
        }
        m = fmaxf(m, __shfl_xor_sync(0xffffffffu, m, 1));
        m = fmaxf(m, __shfl_xor_sync(0xffffffffu, m, 2));
        if (act && sub == 0) { sL4[og] = m; sP[og] = m; }
    }
    {
        int og = t >> 3, sub = t & 7;
        bool act = (og < 27);
        float m = -1e30f;
        if (act) {
            int c = og / 9, rem = og % 9, i = rem / 3, j = rem % 3;
            const float* base = sF + c * 2304 + (i * 16 + sub * 2) * 48 + j * 16;
            #pragma unroll
            for (int r = 0; r < 2; r++)
                #pragma unroll
                for (int q = 0; q < 16; q++) m = fmaxf(m, base[r * 48 + q]);
        }
        m = fmaxf(m, __shfl_xor_sync(0xffffffffu, m, 1));
        m = fmaxf(m, __shfl_xor_sync(0xffffffffu, m, 2));
        m = fmaxf(m, __shfl_xor_sync(0xffffffffu, m, 4));
        if (act && sub == 0) sP[48 + og] = m;
    }
    __syncthreads();
    if (t < 12) {
        int c = t >> 2, rem = t & 3, i = rem >> 1, j = rem & 1;
        const float* L = sL4 + c * 16;
        float m = fmaxf(fmaxf(L[(2 * i) * 4 + 2 * j], L[(2 * i) * 4 + 2 * j + 1]),
                        fmaxf(L[(2 * i + 1) * 4 + 2 * j], L[(2 * i + 1) * 4 + 2 * j + 1]));
        sP[75 + t] = m;
    } else if (t < 15) {
        int c = t - 12;
        float m = -1e30f;
        #pragma unroll
        for (int q = 0; q < 16; q++) m = fmaxf(m, sL4[c * 16 + q]);
        sP[87 + c] = m;
    }
    __syncthreads();
    if (t < 90) {
        float v = sP[t];
        out_pooled[(size_t)n * 90 + t] = v;
        float a0 = bf[t], a1 = 0.f;
        const float* wr = Wf + t * 90;
        #pragma unroll
        for (int k = 0; k < 90; k += 2) {
            a0 = fmaf(sP[k], wr[k], a0);
            a1 = fmaf(sP[k + 1], wr[k + 1], a1);
        }
        float acc = a0 + a1;
        out_fpooled[(size_t)n * 90 + t] = acc;
        __nv_bfloat16 h, l;
        split_bf16(v, h, l);
        gA1h[(size_t)n * 96 + t] = h;
        gA1l[(size_t)n * 96 + t] = l;
        split_bf16(acc, h, l);
        gA1h[(size_t)(NF + n) * 96 + t] = h;
        gA1l[(size_t)(NF + n) * 96 + t] = l;
    } else if (t < 96) {
        __nv_bfloat16 z = __float2bfloat16(0.f);
        gA1h[(size_t)n * 96 + t] = z;
        gA1l[(size_t)n * 96 + t] = z;
        gA1h[(size_t)(NF + n) * 96 + t] = z;
        gA1l[(size_t)(NF + n) * 96 + t] = z;
    }
}

// ============== prep kernels ==============
__global__ __launch_bounds__(256) void k_prepW1(const float* __restrict__ W1) {
    int r = blockIdx.x * 8 + (threadIdx.x >> 5);
    int lane = threadIdx.x & 31;
    const float* src = W1 + (size_t)r * 90;
    #pragma unroll
    for (int it = 0; it < 3; it++) {
        int k = it * 32 + lane;
        float x = (k < 90) ? src[k] : 0.f;
        __nv_bfloat16 h, l;
        split_bf16(x, h, l);
        gW1h[(size_t)r * 96 + k] = h;
        gW1l[(size_t)r * 96 + k] = l;
    }
}
__global__ __launch_bounds__(256) void k_prepB2(const float* __restrict__ F) {
    for (int i = blockIdx.x * 256 + threadIdx.x; i < 64 * EDIM; i += gridDim.x * 256) {
        __nv_bfloat16 h, l;
        split_bf16(F[i], h, l);
        gB2h[i] = h;
        gB2l[i] = l;
    }
}

// ============== FUSED MLP: emb = relu(relu(P@W1^T+b1)@fc7^T + b7) ==============
// 128 rows per CTA, 512 threads. hid never touches gmem.
// smem layout (bytes from base):
//   A1h 0, A1l 26624, W1h 53248, W1l 79872,
//   Sh 106496, Sl 124928  (hid stage, [128][72] bf16 each)
//   B2 143360 + buf*34816 (+17408 for lo)   -> total 212992
#define MLP_SMEM 212992
#define OFF_A1 0u
#define OFF_W1 53248u
#define OFF_SH 106496u
#define OFF_SL 124928u
#define OFF_B2 143360u
__global__ __launch_bounds__(512) void k_mlp(const float* __restrict__ b1,
                                             const float* __restrict__ b7) {
    extern __shared__ __align__(16) char dsm[];
    __shared__ float sBias2[64];
    const int t = threadIdx.x, lane = t & 31, wid = t >> 5;
    const int rb = blockIdx.x * 128;
    const uint32_t base = smem_to_u32(dsm);
    if (t < 64) sBias2[t] = b7[t];

    // initial async loads: A1 tile + W1 chunk0 + B2 chunk0
    #pragma unroll
    for (int i = t; i < 3072; i += 512) {
        int arr = i >= 1536;
        int idx = i - arr * 1536;
        int r = idx / 12, c8 = (idx % 12) * 8;
        cp_async16(base + OFF_A1 + (uint32_t)(arr * 26624) + (uint32_t)(r * 104 + c8) * 2,
                   (arr ? gA1l : gA1h) + (size_t)(rb + r) * 96 + c8);
        cp_async16(base + OFF_W1 + (uint32_t)(arr * 26624) + (uint32_t)(r * 104 + c8) * 2,
                   (arr ? gW1l : gW1h) + (size_t)r * 96 + c8);
    }
    #pragma unroll
    for (int i = t; i < 2048; i += 512) {
        int arr = i >> 10, idx = i & 1023;
        int r = idx >> 4, c8 = (idx & 15) << 3;
        cp_async16(base + OFF_B2 + (uint32_t)(arr * 17408) + (uint32_t)(r * 136 + c8) * 2,
                   (arr ? gB2l : gB2h) + (size_t)r * EDIM + c8);
    }
    CP_COMMIT();

    // g1 warp mapping: 4x4 grid, 32x32 tiles
    const int wm = wid >> 2, wn = wid & 3;
    // g2 warp mapping: 8x2 grid, 16x32 tiles
    const int wm2 = wid >> 1, wn2 = wid & 1;
    const int j = lane >> 3;
    const uint32_t a1Off = OFF_A1 + (uint32_t)((wm * 32 + (lane & 15)) * 104 + ((lane >> 4) << 3)) * 2;
    const uint32_t w1Off = OFF_W1 + (uint32_t)((wn * 32 + ((j >> 1) << 3) + (lane & 7)) * 104 + ((j & 1) << 3)) * 2;
    const uint32_t stOff = OFF_SH + (uint32_t)((wm2 * 16 + (lane & 15)) * 72 + ((lane >> 4) << 3)) * 2;
    const uint32_t b2Off = (uint32_t)((wn2 * 32 + ((j >> 1) << 3) + (lane & 7)) * 136 + ((j & 1) << 3)) * 2;

    float acc2[4][4];
    #pragma unroll
    for (int nt = 0; nt < 4; nt++)
        #pragma unroll
        for (int q = 0; q < 4; q++) acc2[nt][q] = 0.f;

    const int g = lane >> 2, i2 = (lane & 3) * 2;

    for (int c = 0; c < 32; c++) {
        CP_WAIT0();
        __syncthreads();

        // ---- g1 mma: 3-pass fused (frag reuse), K=96 ----
        float acc1[2][4][4];
        #pragma unroll
        for (int mi = 0; mi < 2; mi++)
            #pragma unroll
            for (int nt = 0; nt < 4; nt++)
                #pragma unroll
                for (int q = 0; q < 4; q++) acc1[mi][nt][q] = 0.f;
        #pragma unroll
        for (int kk = 0; kk < 6; kk++) {
            uint32_t ah[2][4], al[2][4];
            ldsm4(ah[0], base + a1Off + kk * 32);
            ldsm4(ah[1], base + a1Off + (16 * 104 * 2) + kk * 32);
            ldsm4(al[0], base + a1Off + 26624u + kk * 32);
            ldsm4(al[1], base + a1Off + 26624u + (16 * 104 * 2) + kk * 32);
            #pragma unroll
            for (int nt2 = 0; nt2 < 2; nt2++) {
                uint32_t bh[4], bl[4];
                ldsm4(bh, base + w1Off + (uint32_t)(nt2 * 16 * 104 * 2) + kk * 32);
                ldsm4(bl, base + w1Off + 26624u + (uint32_t)(nt2 * 16 * 104 * 2) + kk * 32);
                #pragma unroll
                for (int mi = 0; mi < 2; mi++) {
                    mma_bf16(acc1[mi][nt2 * 2],     ah[mi], bh);
                    mma_bf16(acc1[mi][nt2 * 2 + 1], ah[mi], bh + 2);
                    mma_bf16(acc1[mi][nt2 * 2],     al[mi], bh);
                    mma_bf16(acc1[mi][nt2 * 2 + 1], al[mi], bh + 2);
                    mma_bf16(acc1[mi][nt2 * 2],     ah[mi], bl);
                    mma_bf16(acc1[mi][nt2 * 2 + 1], ah[mi], bl + 2);
                }
            }
        }
        __syncthreads();   // everyone done reading W1 chunk

        // prefetch next W1 + B2 chunk (other B2 buffer)
        if (c + 1 < 32) {
            const int jbN = (c + 1) * 128;
            #pragma unroll
            for (int i = t; i < 3072; i += 512) {
                int arr = i >= 1536;
                int idx = i - arr * 1536;
                int r = idx / 12, c8 = (idx % 12) * 8;
                cp_async16(base + OFF_W1 + (uint32_t)(arr * 26624) + (uint32_t)(r * 104 + c8) * 2,
                           (arr ? gW1l : gW1h) + (size_t)(jbN + r) * 96 + c8);
            }
            const int kcN = (c + 1) * 128;
            const uint32_t bbN = OFF_B2 + (uint32_t)(((c + 1) & 1) * 34816);
            #pragma unroll
            for (int i = t; i < 2048; i += 512) {
                int arr = i >> 10, idx = i & 1023;
                int r = idx >> 4, c8 = (idx & 15) << 3;
                cp_async16(base + bbN + (uint32_t)(arr * 17408) + (uint32_t)(r * 136 + c8) * 2,
                           (arr ? gB2l : gB2h) + (size_t)r * EDIM + kcN + c8);
            }
            CP_COMMIT();
        }

        const uint32_t b2buf = OFF_B2 + (uint32_t)((c & 1) * 34816);
        // ---- two 64-col halves: stage hid, then g2 mma ----
        #pragma unroll
        for (int h = 0; h < 2; h++) {
            if ((wn >> 1) == h) {
                __nv_bfloat16* sSh = (__nv_bfloat16*)(dsm + OFF_SH);
                __nv_bfloat16* sSl = (__nv_bfloat16*)(dsm + OFF_SL);
                #pragma unroll
                for (int mi = 0; mi < 2; mi++)
                    #pragma unroll
                    for (int nt = 0; nt < 4; nt++) {
                        int row = wm * 32 + mi * 16 + g;
                        int ccol = wn * 32 + nt * 8 + i2;       // chunk col 0..127
                        int lcol = ccol - h * 64;               // 0..63
                        float bv0 = b1[c * 128 + ccol], bv1 = b1[c * 128 + ccol + 1];
                        float v0 = fmaxf(acc1[mi][nt][0] + bv0, 0.f);
                        float v1 = fmaxf(acc1[mi][nt][1] + bv1, 0.f);
                        float v2 = fmaxf(acc1[mi][nt][2] + bv0, 0.f);
                        float v3 = fmaxf(acc1[mi][nt][3] + bv1, 0.f);
                        __nv_bfloat16 h0, l0, h1, l1;
                        split_bf16(v0, h0, l0); split_bf16(v1, h1, l1);
                        *(uint32_t*)(sSh + row * 72 + lcol) =
                            (uint32_t)__bfloat16_as_ushort(h1) << 16 | __bfloat16_as_ushort(h0);
                        *(uint32_t*)(sSl + row * 72 + lcol) =
                            (uint32_t)__bfloat16_as_ushort(l1) << 16 | __bfloat16_as_ushort(l0);
                        split_bf16(v2, h0, l0); split_bf16(v3, h1, l1);
                        *(uint32_t*)(sSh + (row + 8) * 72 + lcol) =
                            (uint32_t)__bfloat16_as_ushort(h1) << 16 | __bfloat16_as_ushort(h0);
                        *(uint32_t*)(sSl + (row + 8) * 72 + lcol) =
                            (uint32_t)__bfloat16_as_ushort(l1) << 16 | __bfloat16_as_ushort(l0);
                    }
            }
            __syncthreads();
            // g2 mma: K=64, stage + B2[buf] cols h*64..
            #pragma unroll
            for (int kk = 0; kk < 4; kk++) {
                uint32_t ah[4], al[4];
                ldsm4(ah, base + stOff + kk * 32);
                ldsm4(al, base + stOff + (OFF_SL - OFF_SH) + kk * 32);
                #pragma unroll
                for (int nt2 = 0; nt2 < 2; nt2++) {
                    uint32_t bh[4], bl[4];
                    uint32_t boff = base + b2buf + b2Off + (uint32_t)(nt2 * 16 * 136 * 2) + (uint32_t)(h * 128) + kk * 32;
                    ldsm4(bh, boff);
                    ldsm4(bl, boff + 17408u);
                    mma_bf16(acc2[nt2 * 2],     ah, bh);
                    mma_bf16(acc2[nt2 * 2 + 1], ah, bh + 2);
                    mma_bf16(acc2[nt2 * 2],     al, bh);
                    mma_bf16(acc2[nt2 * 2 + 1], al, bh + 2);
                    mma_bf16(acc2[nt2 * 2],     ah, bl);
                    mma_bf16(acc2[nt2 * 2 + 1], ah, bl + 2);
                }
            }
            __syncthreads();   // stage free for next half / chunk
        }
    }

    // ---- epilogue: bias2 + relu -> g_emb (reuse A1 region as fp32 stage [128][68]) ----
    float* stage = (float*)dsm;
    #pragma unroll
    for (int nt = 0; nt < 4; nt++) {
        int row = wm2 * 16 + g;
        int col = wn2 * 32 + nt * 8 + i2;
        stage[row * 68 + col]           = fmaxf(acc2[nt][0] + sBias2[col], 0.f);
        stage[row * 68 + col + 1]       = fmaxf(acc2[nt][1] + sBias2[col + 1], 0.f);
        stage[(row + 8) * 68 + col]     = fmaxf(acc2[nt][2] + sBias2[col], 0.f);
        stage[(row + 8) * 68 + col + 1] = fmaxf(acc2[nt][3] + sBias2[col + 1], 0.f);
    }
    __syncthreads();
    for (int i = t; i < 2048; i += 512) {
        int r = i >> 4, c4 = (i & 15) << 2;
        *(float4*)&g_emb[(size_t)(rb + r) * 64 + c4] = *(float4*)&stage[r * 68 + c4];
    }
}

// ============== k_x (unchanged) ==============
__global__ __launch_bounds__(256) void k_x(const float* __restrict__ wih,
                                           const float* __restrict__ bih,
                                           const float* __restrict__ bhh) {
    extern __shared__ float smx[];
    float* sAT = smx;
    float* sWT = smx + 64 * 68;
    const int t = threadIdx.x;
    const int rb = blockIdx.y * 64;
    const int jb = blockIdx.x * 128;
    #pragma unroll
    for (int i = t; i < 1024; i += 256) {
        int q = i >> 6, r = i & 63;
        float4 v = *reinterpret_cast<const float4*>(&g_emb[(size_t)(rb + r) * 64 + q * 4]);
        sAT[(q * 4 + 0) * 68 + r] = v.x;
        sAT[(q * 4 + 1) * 68 + r] = v.y;
        sAT[(q * 4 + 2) * 68 + r] = v.z;
        sAT[(q * 4 + 3) * 68 + r] = v.w;
    }
    #pragma unroll
    for (int i = t; i < 2048; i += 256) {
        int kq = i >> 7, j = i & 127;
        float4 v = *reinterpret_cast<const float4*>(&wih[(size_t)(jb + j) * 64 + kq * 4]);
        sWT[(kq * 4 + 0) * 128 + j] = v.x;
        sWT[(kq * 4 + 1) * 128 + j] = v.y;
        sWT[(kq * 4 + 2) * 128 + j] = v.z;
        sWT[(kq * 4 + 3) * 128 + j] = v.w;
    }
    __syncthreads();
    const int jj = t & 31, rr = t >> 5;
    const int j = jj * 4, r0 = rr * 8;
    unsigned long long acc[4][4];
    #pragma unroll
    for (int p = 0; p < 4; p++)
        #pragma unroll
        for (int q = 0; q < 4; q++) acc[p][q] = 0ULL;
    #pragma unroll 16
    for (int k = 0; k < 64; k++) {
        const ulonglong2* pa = reinterpret_cast<const ulonglong2*>(sAT + k * 68 + r0);
        ulonglong2 a01 = pa[0], a23 = pa[1];
        unsigned long long a[4] = {a01.x, a01.y, a23.x, a23.y};
        float4 wv = *reinterpret_cast<const float4*>(sWT + k * 128 + j);
        unsigned long long w[4] = {pack2(wv.x), pack2(wv.y), pack2(wv.z), pack2(wv.w)};
        #pragma unroll
        for (int p = 0; p < 4; p++)
            #pragma unroll
            for (int q = 0; q < 4; q++) acc[p][q] = ffma2(a[p], w[q], acc[p][q]);
    }
    float4 bi = *reinterpret_cast<const float4*>(&bih[jb + j]);
    float4 bh = *reinterpret_cast<const float4*>(&bhh[jb + j]);
    float4 bv = make_float4(bi.x + bh.x, bi.y + bh.y, bi.z + bh.z, bi.w + bh.w);
    #pragma unroll
    for (int p = 0; p < 4; p++) {
        float x0, y0, x1, y1, x2, y2, x3, y3;
        unpack2(acc[p][0], x0, y0);
        unpack2(acc[p][1], x1, y1);
        unpack2(acc[p][2], x2, y2);
        unpack2(acc[p][3], x3, y3);
        float4 rA = make_float4(x0 + bv.x, x1 + bv.y, x2 + bv.z, x3 + bv.w);
        float4 rB = make_float4(y0 + bv.x, y1 + bv.y, y2 + bv.z, y3 + bv.w);
        int rowA = rb + r0 + 2 * p;
        int rowB = rowA + 1;
        {
            int branch = rowA >> 13, n = rowA & 8191, b = n >> 9, s = n & 511;
            size_t dst = ((size_t)branch * NF + (size_t)s * 16 + b) * 256 + jb + j;
            *reinterpret_cast<float4*>(&g_X[dst]) = rA;
        }
        {
            int branch = rowB >> 13, n = rowB & 8191, b = n >> 9, s = n & 511;
            size_t dst = ((size_t)branch * NF + (size_t)s * 16 + b) * 256 + jb + j;
            *reinterpret_cast<float4*>(&g_X[dst]) = rB;
        }
    }
}

// ============== k_lstm (quad-gate mapping, 2 syncs/step) ==============
__global__ __launch_bounds__(256) void k_lstm(const float* __restrict__ whh1,
                                              const float* __restrict__ wih2,
                                              const float* __restrict__ whh2,
                                              const float* __restrict__ bih2,
                                              const float* __restrict__ bhh2) {
    __shared__ __align__(16) float sxin[192];
    const int b = blockIdx.x, t = threadIdx.x;
    const int u = t >> 2, q = t & 3;
    const int gi = q * 64 + u;

    float w1[64];
    #pragma unroll
    for (int k = 0; k < 64; k++) w1[k] = whh1[gi * 64 + k];

    const int v = (t >> 2) & 31;
    const int gi2 = q * 32 + v;
    float w2i[64], w2h[32];
    float b2 = 0.f;
    if (t < 128) {
        #pragma unroll
        for (int k = 0; k < 64; k++) w2i[k] = wih2[gi2 * 64 + k];
        #pragma unroll
        for (int k = 0; k < 32; k++) w2h[k] = whh2[gi2 * 32 + k];
        b2 = bih2[gi2] + bhh2[gi2];
    }

    float c1 = 0.f, c2 = 0.f;
    if (t < 192) sxin[t] = 0.f;
    __syncthreads();

    const float* xbase = g_X + (size_t)b * 256;
    float xg = xbase[gi];
    const int lanebase = t & ~3;

    for (int s = 0; s < 512; s++) {
        float xn = (s < 511) ? xbase[(size_t)(s + 1) * 4096 + gi] : 0.f;
        const int p = s & 1;
        const float4* h1rd = (const float4*)(sxin + 64 * p);
        const float4* h1nw = (const float4*)(sxin + 64 * (1 - p));
        const float4* h2rd = (const float4*)(sxin + 128 + 32 * p);

        float a0 = xg, a1 = 0.f, a2 = 0.f, a3 = 0.f;
        #pragma unroll
        for (int k = 0; k < 16; k++) {
            float4 hv = h1rd[k];
            a0 = fmaf(hv.x, w1[4 * k],     a0);
            a1 = fmaf(hv.y, w1[4 * k + 1], a1);
            a2 = fmaf(hv.z, w1[4 * k + 2], a2);
            a3 = fmaf(hv.w, w1[4 * k + 3], a3);
        }
        float av = (a0 + a1) + (a2 + a3);
        float gv = (q == 2) ? tanh_f(av) : sigf(av);
        float vi = __shfl_sync(0xffffffffu, gv, lanebase);
        float vf = __shfl_sync(0xffffffffu, gv, lanebase + 1);
        float vg = __shfl_sync(0xffffffffu, gv, lanebase + 2);
        float vo = __shfl_sync(0xffffffffu, gv, lanebase + 3);
        if (q == 0) {
            c1 = vf * c1 + vi * vg;
            float h1v = vo * tanh_f(c1);
            sxin[64 * (1 - p) + u] = h1v;
            g_H1[((size_t)s * 16 + b) * 64 + u] = h1v;
            g_C1[((size_t)s * 16 + b) * 64 + u] = c1;
        }
        __syncthreads();

        if (t < 128) {
            float p0 = b2, p1 = 0.f, p2 = 0.f, p3 = 0.f;
            #pragma unroll
            for (int k = 0; k < 16; k++) {
                float4 hv = h1nw[k];
                p0 = fmaf(hv.x, w2i[4 * k],     p0);
                p1 = fmaf(hv.y, w2i[4 * k + 1], p1);
                p2 = fmaf(hv.z, w2i[4 * k + 2], p2);
                p3 = fmaf(hv.w, w2i[4 * k + 3], p3);
            }
            #pragma unroll
            for (int k = 0; k < 8; k++) {
                float4 hv = h2rd[k];
                p0 = fmaf(hv.x, w2h[4 * k],     p0);
                p1 = fmaf(hv.y, w2h[4 * k + 1], p1);
                p2 = fmaf(hv.z, w2h[4 * k + 2], p2);
                p3 = fmaf(hv.w, w2h[4 * k + 3], p3);
            }
            float pv = (p0 + p1) + (p2 + p3);
            float g2v = (q == 2) ? tanh_f(pv) : sigf(pv);
            float wi = __shfl_sync(0xffffffffu, g2v, lanebase);
            float wf = __shfl_sync(0xffffffffu, g2v, lanebase + 1);
            float wg = __shfl_sync(0xffffffffu, g2v, lanebase + 2);
            float wo = __shfl_sync(0xffffffffu, g2v, lanebase + 3);
            if (q == 0) {
                c2 = wf * c2 + wi * wg;
                float h2v = wo * tanh_f(c2);
                sxin[128 + 32 * (1 - p) + v] = h2v;
                g_H2[((size_t)s * 16 + b) * 32 + v] = h2v;
                g_C2[((size_t)s * 16 + b) * 32 + v] = c2;
            }
        }
        xg = xn;
        __syncthreads();
    }
}

// ============== k_f (unchanged) ==============
__global__ __launch_bounds__(256) void k_f(const float* __restrict__ whh1,
                                           const float* __restrict__ wih2,
                                           const float* __restrict__ whh2,
                                           const float* __restrict__ bih2,
                                           const float* __restrict__ bhh2,
                                           const float* __restrict__ fc8w,
                                           const float* __restrict__ fc8b,
                                           float* __restrict__ out_prog,
                                           float* __restrict__ out_fprog) {
    extern __shared__ float smf[];
    float* w1T  = smf;
    float* wi2T = w1T + 64 * 256;
    float* wh2T = wi2T + 64 * 128;
    float* b2s  = wh2T + 32 * 128;
    float* sH1  = b2s + 128;
    float* sC1  = sH1 + 1024;
    float* sH2  = sC1 + 1024;
    float* sC2  = sH2 + 512;
    float* sG1  = sC2 + 512;
    float* sFh1 = sG1 + 4096;
    float* sG2  = sFh1 + 1024;
    float* sFh2 = sG2 + 2048;
    const int t = threadIdx.x;
    const int s = blockIdx.x;
    const size_t r0 = (size_t)s * 16;
    for (int i = t; i < 64 * 256; i += 256) {
        int k = i >> 8, g = i & 255;
        w1T[i] = whh1[g * 64 + k];
    }
    for (int i = t; i < 64 * 128; i += 256) {
        int k = i >> 7, g = i & 127;
        wi2T[i] = wih2[g * 64 + k];
    }
    for (int i = t; i < 32 * 128; i += 256) {
        int k = i >> 7, g = i & 127;
        wh2T[i] = whh2[g * 32 + k];
    }
    if (t < 128) b2s[t] = bih2[t] + bhh2[t];
    for (int i = t; i < 1024; i += 256) sH1[i] = g_H1[r0 * 64 + i];
    for (int i = t; i < 1024; i += 256) sC1[i] = g_C1[r0 * 64 + i];
    for (int i = t; i < 512;  i += 256) sH2[i] = g_H2[r0 * 32 + i];
    for (int i = t; i < 512;  i += 256) sC2[i] = g_C2[r0 * 32 + i];
    for (int i = t; i < 4096; i += 256) sG1[i] = g_X[(size_t)NF * 256 + r0 * 256 + i];
    __syncthreads();
    {
        float acc[16];
        #pragma unroll
        for (int r = 0; r < 16; r++) acc[r] = sG1[r * 256 + t];
        #pragma unroll 8
        for (int k = 0; k < 64; k++) {
            float w = w1T[k * 256 + t];
            #pragma unroll
            for (int r = 0; r < 16; r++) acc[r] = fmaf(sH1[r * 64 + k], w, acc[r]);
        }
        bool is_g = ((t >> 6) == 2);
        #pragma unroll
        for (int r = 0; r < 16; r++)
            sG1[r * 256 + t] = is_g ? tanhf(acc[r]) : sigf(acc[r]);
    }
    __syncthreads();
    for (int i = t; i < 1024; i += 256) {
        int r = i >> 6, u = i & 63;
        const float* g = sG1 + r * 256;
        float c = g[64 + u] * sC1[r * 64 + u] + g[u] * g[128 + u];
        sFh1[r * 64 + u] = g[192 + u] * tanhf(c);
    }
    __syncthreads();
    if (t < 128) {
        float acc[16];
        #pragma unroll
        for (int r = 0; r < 16; r++) acc[r] = b2s[t];
        #pragma unroll 8
        for (int k = 0; k < 64; k++) {
            float w = wi2T[k * 128 + t];
            #pragma unroll
            for (int r = 0; r < 16; r++) acc[r] = fmaf(sFh1[r * 64 + k], w, acc[r]);
        }
        #pragma unroll 8
        for (int k = 0; k < 32; k++) {
            float w = wh2T[k * 128 + t];
            #pragma unroll
            for (int r = 0; r < 16; r++) acc[r] = fmaf(sH2[r * 32 + k], w, acc[r]);
        }
        bool is_g = ((t >> 5) == 2);
        #pragma unroll
        for (int r = 0; r < 16; r++)
            sG2[r * 128 + t] = is_g ? tanhf(acc[r]) : sigf(acc[r]);
    }
    __syncthreads();
    for (int i = t; i < 512; i += 256) {
        int r = i >> 5, u = i & 31;
        const float* g = sG2 + r * 128;
        float c = g[32 + u] * sC2[r * 32 + u] + g[u] * g[64 + u];
        sFh2[r * 32 + u] = g[96 + u] * tanhf(c);
    }
    __syncthreads();
    if (t < 32) {
        int r = t >> 1, which = t & 1;
        const float* v = which ? (sFh2 + r * 32) : (sH2 + r * 32);
        float acc = fc8b[0];
        #pragma unroll
        for (int k = 0; k < 32; k++) acc = fmaf(v[k], fc8w[k], acc);
        float ov = sigf(acc);
        int b = r;
        if (which) out_fprog[(size_t)b * 512 + s] = ov;
        else       out_prog[(size_t)b * 512 + s] = ov;
    }
}

// =====================================================================
extern "C" void kernel_launch(void* const* d_in, const int* in_sizes, int n_in,
                              void* d_out, int out_size) {
    const float* frames  = (const float*)d_in[0];
    const float* spp_w   = (const float*)d_in[1];
    const float* spp_b   = (const float*)d_in[2];
    const float* fore_w  = (const float*)d_in[3];
    const float* fore_b  = (const float*)d_in[4];
    const float* fc7_w   = (const float*)d_in[5];
    const float* fc7_b   = (const float*)d_in[6];
    const float* l1_wih  = (const float*)d_in[7];
    const float* l1_whh  = (const float*)d_in[8];
    const float* l1_bih  = (const float*)d_in[9];
    const float* l1_bhh  = (const float*)d_in[10];
    const float* l2_wih  = (const float*)d_in[11];
    const float* l2_whh  = (const float*)d_in[12];
    const float* l2_bih  = (const float*)d_in[13];
    const float* l2_bhh  = (const float*)d_in[14];
    const float* fc8_w   = (const float*)d_in[15];
    const float* fc8_b   = (const float*)d_in[16];

    float* out         = (float*)d_out;
    float* out_prog    = out;
    float* out_fprog   = out + 8192;
    float* out_pooled  = out + 16384;
    float* out_fpooled = out + 16384 + 737280;

    const int smem_x = (64 * 68 + 64 * 128) * 4;
    const int smem_f = (64 * 256 + 64 * 128 + 32 * 128 + 128 +
                        1024 + 1024 + 512 + 512 + 4096 + 1024 + 2048 + 512) * 4;
    cudaFuncSetAttribute(k_mlp, cudaFuncAttributeMaxDynamicSharedMemorySize, MLP_SMEM);
    cudaFuncSetAttribute(k_x,   cudaFuncAttributeMaxDynamicSharedMemorySize, smem_x);
    cudaFuncSetAttribute(k_f,   cudaFuncAttributeMaxDynamicSharedMemorySize, smem_f);

    k_spp<<<NF, 256>>>(frames, fore_w, fore_b, out_pooled, out_fpooled);
    k_prepW1<<<EDIM / 8, 256>>>(spp_w);
    k_prepB2<<<64, 256>>>(fc7_w);
    k_mlp<<<128, 512, MLP_SMEM>>>(spp_b, fc7_b);
    k_x<<<dim3(2, 256), 256, smem_x>>>(l1_wih, l1_bih, l1_bhh);
    k_lstm<<<16, 256>>>(l1_whh, l2_wih, l2_whh, l2_bih, l2_bhh);
    k_f<<<512, 256, smem_f>>>(l1_whh, l2_wih, l2_whh, l2_bih, l2_bhh, fc8_w, fc8_b,
                              out_prog, out_fprog);
}

// round 15
// speedup vs baseline: 1.1071x; 1.1071x over previous
#include <cuda_runtime.h>
#include <cuda_bf16.h>
#include <cstdint>

#define NF    8192
#define NROWS 16384
#define EDIM  4096

__device__ float g_emb[NROWS * 64];
__device__ float g_X[2 * NF * 256];
__device__ float g_H1[512 * 16 * 64];
__device__ float g_C1[512 * 16 * 64];
__device__ float g_H2[512 * 16 * 32];
__device__ float g_C2[512 * 16 * 32];
__device__ __nv_bfloat16 gA1h[(size_t)NROWS * 96];
__device__ __nv_bfloat16 gA1l[(size_t)NROWS * 96];
__device__ __nv_bfloat16 gW1h[(size_t)EDIM * 96];
__device__ __nv_bfloat16 gW1l[(size_t)EDIM * 96];
__device__ __nv_bfloat16 gB2h[64 * EDIM];
__device__ __nv_bfloat16 gB2l[64 * EDIM];

__device__ __forceinline__ uint32_t smem_to_u32(const void* p) {
    uint32_t a;
    asm("{ .reg .u64 t; cvta.to.shared.u64 t, %1; cvt.u32.u64 %0, t; }" : "=r"(a) : "l"(p));
    return a;
}
__device__ __forceinline__ void ldsm4(uint32_t* r, uint32_t addr) {
    asm volatile("ldmatrix.sync.aligned.m8n8.x4.shared.b16 {%0,%1,%2,%3}, [%4];"
                 : "=r"(r[0]), "=r"(r[1]), "=r"(r[2]), "=r"(r[3]) : "r"(addr));
}
__device__ __forceinline__ void mma_bf16(float* d, const uint32_t* a, const uint32_t* b) {
    asm volatile("mma.sync.aligned.m16n8k16.row.col.f32.bf16.bf16.f32 "
                 "{%0,%1,%2,%3}, {%4,%5,%6,%7}, {%8,%9}, {%0,%1,%2,%3};"
                 : "+f"(d[0]), "+f"(d[1]), "+f"(d[2]), "+f"(d[3])
                 : "r"(a[0]), "r"(a[1]), "r"(a[2]), "r"(a[3]), "r"(b[0]), "r"(b[1]));
}
__device__ __forceinline__ void cp_async16(uint32_t saddr, const void* g) {
    asm volatile("cp.async.cg.shared.global [%0], [%1], 16;" :: "r"(saddr), "l"(g));
}
#define CP_COMMIT() asm volatile("cp.async.commit_group;" ::: "memory")
#define CP_WAIT0()  asm volatile("cp.async.wait_group 0;" ::: "memory")
#define BAR512()    asm volatile("bar.sync 0, 512;" ::: "memory")
__device__ __forceinline__ unsigned long long ffma2(unsigned long long a, unsigned long long b, unsigned long long c) {
    unsigned long long d;
    asm("fma.rn.f32x2 %0, %1, %2, %3;" : "=l"(d) : "l"(a), "l"(b), "l"(c));
    return d;
}
__device__ __forceinline__ unsigned long long pack2(float x) {
    unsigned long long d;
    unsigned int u = __float_as_uint(x);
    asm("mov.b64 %0, {%1, %1};" : "=l"(d) : "r"(u));
    return d;
}
__device__ __forceinline__ void unpack2(unsigned long long v, float& lo, float& hi) {
    unsigned int a, b;
    asm("mov.b64 {%0, %1}, %2;" : "=r"(a), "=r"(b) : "l"(v));
    lo = __uint_as_float(a);
    hi = __uint_as_float(b);
}
__device__ __forceinline__ float sigf(float x) { return 1.0f / (1.0f + __expf(-x)); }
__device__ __forceinline__ float tanh_f(float x) { return 1.0f - 2.0f / (__expf(2.0f * x) + 1.0f); }
__device__ __forceinline__ void split_bf16(float x, __nv_bfloat16& h, __nv_bfloat16& l) {
    h = __float2bfloat16(x);
    l = __float2bfloat16(x - __bfloat162float(h));
}

// ============== k_spp (emits gA1 hi/lo split directly) ==============
__global__ __launch_bounds__(256) void k_spp(const float* __restrict__ frames,
                                             const float* __restrict__ Wf,
                                             const float* __restrict__ bf,
                                             float* __restrict__ out_pooled,
                                             float* __restrict__ out_fpooled) {
    __shared__ float sF[3 * 48 * 48];
    __shared__ float sL4[48];
    __shared__ float sP[90];
    const int n = blockIdx.x, t = threadIdx.x;
    const float4* src = reinterpret_cast<const float4*>(frames + (size_t)n * 6912);
    float4* dst = reinterpret_cast<float4*>(sF);
    #pragma unroll
    for (int i = t; i < 1728; i += 256) dst[i] = src[i];
    __syncthreads();
    {
        int og = t >> 2, sub = t & 3;
        bool act = (og < 48);
        float m = -1e30f;
        if (act) {
            int c = og >> 4, rem = og & 15, i = rem >> 2, j = rem & 3;
            const float* base = sF + c * 2304 + (i * 12 + sub * 3) * 48 + j * 12;
            #pragma unroll
            for (int r = 0; r < 3; r++)
                #pragma unroll
                for (int q = 0; q < 12; q++) m = fmaxf(m, base[r * 48 + q]);
        }
        m = fmaxf(m, __shfl_xor_sync(0xffffffffu, m, 1));
        m = fmaxf(m, __shfl_xor_sync(0xffffffffu, m, 2));
        if (act && sub == 0) { sL4[og] = m; sP[og] = m; }
    }
    {
        int og = t >> 3, sub = t & 7;
        bool act = (og < 27);
        float m = -1e30f;
        if (act) {
            int c = og / 9, rem = og % 9, i = rem / 3, j = rem % 3;
            const float* base = sF + c * 2304 + (i * 16 + sub * 2) * 48 + j * 16;
            #pragma unroll
            for (int r = 0; r < 2; r++)
                #pragma unroll
                for (int q = 0; q < 16; q++) m = fmaxf(m, base[r * 48 + q]);
        }
        m = fmaxf(m, __shfl_xor_sync(0xffffffffu, m, 1));
        m = fmaxf(m, __shfl_xor_sync(0xffffffffu, m, 2));
        m = fmaxf(m, __shfl_xor_sync(0xffffffffu, m, 4));
        if (act && sub == 0) sP[48 + og] = m;
    }
    __syncthreads();
    if (t < 12) {
        int c = t >> 2, rem = t & 3, i = rem >> 1, j = rem & 1;
        const float* L = sL4 + c * 16;
        float m = fmaxf(fmaxf(L[(2 * i) * 4 + 2 * j], L[(2 * i) * 4 + 2 * j + 1]),
                        fmaxf(L[(2 * i + 1) * 4 + 2 * j], L[(2 * i + 1) * 4 + 2 * j + 1]));
        sP[75 + t] = m;
    } else if (t < 15) {
        int c = t - 12;
        float m = -1e30f;
        #pragma unroll
        for (int q = 0; q < 16; q++) m = fmaxf(m, sL4[c * 16 + q]);
        sP[87 + c] = m;
    }
    __syncthreads();
    if (t < 90) {
        float v = sP[t];
        out_pooled[(size_t)n * 90 + t] = v;
        float a0 = bf[t], a1 = 0.f;
        const float* wr = Wf + t * 90;
        #pragma unroll
        for (int k = 0; k < 90; k += 2) {
            a0 = fmaf(sP[k], wr[k], a0);
            a1 = fmaf(sP[k + 1], wr[k + 1], a1);
        }
        float acc = a0 + a1;
        out_fpooled[(size_t)n * 90 + t] = acc;
        __nv_bfloat16 h, l;
        split_bf16(v, h, l);
        gA1h[(size_t)n * 96 + t] = h;
        gA1l[(size_t)n * 96 + t] = l;
        split_bf16(acc, h, l);
        gA1h[(size_t)(NF + n) * 96 + t] = h;
        gA1l[(size_t)(NF + n) * 96 + t] = l;
    } else if (t < 96) {
        __nv_bfloat16 z = __float2bfloat16(0.f);
        gA1h[(size_t)n * 96 + t] = z;
        gA1l[(size_t)n * 96 + t] = z;
        gA1h[(size_t)(NF + n) * 96 + t] = z;
        gA1l[(size_t)(NF + n) * 96 + t] = z;
    }
}

// ============== prep kernels ==============
__global__ __launch_bounds__(256) void k_prepW1(const float* __restrict__ W1) {
    int r = blockIdx.x * 8 + (threadIdx.x >> 5);
    int lane = threadIdx.x & 31;
    const float* src = W1 + (size_t)r * 90;
    #pragma unroll
    for (int it = 0; it < 3; it++) {
        int k = it * 32 + lane;
        float x = (k < 90) ? src[k] : 0.f;
        __nv_bfloat16 h, l;
        split_bf16(x, h, l);
        gW1h[(size_t)r * 96 + k] = h;
        gW1l[(size_t)r * 96 + k] = l;
    }
}
__global__ __launch_bounds__(256) void k_prepB2(const float* __restrict__ F) {
    for (int i = blockIdx.x * 256 + threadIdx.x; i < 64 * EDIM; i += gridDim.x * 256) {
        __nv_bfloat16 h, l;
        split_bf16(F[i], h, l);
        gB2h[i] = h;
        gB2l[i] = l;
    }
}

// ============== FUSED MLP (unchanged) ==============
#define MLP_SMEM 212992
#define OFF_A1 0u
#define OFF_W1 53248u
#define OFF_SH 106496u
#define OFF_SL 124928u
#define OFF_B2 143360u
__global__ __launch_bounds__(512) void k_mlp(const float* __restrict__ b1,
                                             const float* __restrict__ b7) {
    extern __shared__ __align__(16) char dsm[];
    __shared__ float sBias2[64];
    const int t = threadIdx.x, lane = t & 31, wid = t >> 5;
    const int rb = blockIdx.x * 128;
    const uint32_t base = smem_to_u32(dsm);
    if (t < 64) sBias2[t] = b7[t];

    #pragma unroll
    for (int i = t; i < 3072; i += 512) {
        int arr = i >= 1536;
        int idx = i - arr * 1536;
        int r = idx / 12, c8 = (idx % 12) * 8;
        cp_async16(base + OFF_A1 + (uint32_t)(arr * 26624) + (uint32_t)(r * 104 + c8) * 2,
                   (arr ? gA1l : gA1h) + (size_t)(rb + r) * 96 + c8);
        cp_async16(base + OFF_W1 + (uint32_t)(arr * 26624) + (uint32_t)(r * 104 + c8) * 2,
                   (arr ? gW1l : gW1h) + (size_t)r * 96 + c8);
    }
    #pragma unroll
    for (int i = t; i < 2048; i += 512) {
        int arr = i >> 10, idx = i & 1023;
        int r = idx >> 4, c8 = (idx & 15) << 3;
        cp_async16(base + OFF_B2 + (uint32_t)(arr * 17408) + (uint32_t)(r * 136 + c8) * 2,
                   (arr ? gB2l : gB2h) + (size_t)r * EDIM + c8);
    }
    CP_COMMIT();

    const int wm = wid >> 2, wn = wid & 3;
    const int wm2 = wid >> 1, wn2 = wid & 1;
    const int j = lane >> 3;
    const uint32_t a1Off = OFF_A1 + (uint32_t)((wm * 32 + (lane & 15)) * 104 + ((lane >> 4) << 3)) * 2;
    const uint32_t w1Off = OFF_W1 + (uint32_t)((wn * 32 + ((j >> 1) << 3) + (lane & 7)) * 104 + ((j & 1) << 3)) * 2;
    const uint32_t stOff = OFF_SH + (uint32_t)((wm2 * 16 + (lane & 15)) * 72 + ((lane >> 4) << 3)) * 2;
    const uint32_t b2Off = (uint32_t)((wn2 * 32 + ((j >> 1) << 3) + (lane & 7)) * 136 + ((j & 1) << 3)) * 2;

    float acc2[4][4];
    #pragma unroll
    for (int nt = 0; nt < 4; nt++)
        #pragma unroll
        for (int q = 0; q < 4; q++) acc2[nt][q] = 0.f;

    const int g = lane >> 2, i2 = (lane & 3) * 2;

    for (int c = 0; c < 32; c++) {
        CP_WAIT0();
        __syncthreads();

        float acc1[2][4][4];
        #pragma unroll
        for (int mi = 0; mi < 2; mi++)
            #pragma unroll
            for (int nt = 0; nt < 4; nt++)
                #pragma unroll
                for (int q = 0; q < 4; q++) acc1[mi][nt][q] = 0.f;
        #pragma unroll
        for (int kk = 0; kk < 6; kk++) {
            uint32_t ah[2][4], al[2][4];
            ldsm4(ah[0], base + a1Off + kk * 32);
            ldsm4(ah[1], base + a1Off + (16 * 104 * 2) + kk * 32);
            ldsm4(al[0], base + a1Off + 26624u + kk * 32);
            ldsm4(al[1], base + a1Off + 26624u + (16 * 104 * 2) + kk * 32);
            #pragma unroll
            for (int nt2 = 0; nt2 < 2; nt2++) {
                uint32_t bh[4], bl[4];
                ldsm4(bh, base + w1Off + (uint32_t)(nt2 * 16 * 104 * 2) + kk * 32);
                ldsm4(bl, base + w1Off + 26624u + (uint32_t)(nt2 * 16 * 104 * 2) + kk * 32);
                #pragma unroll
                for (int mi = 0; mi < 2; mi++) {
                    mma_bf16(acc1[mi][nt2 * 2],     ah[mi], bh);
                    mma_bf16(acc1[mi][nt2 * 2 + 1], ah[mi], bh + 2);
                    mma_bf16(acc1[mi][nt2 * 2],     al[mi], bh);
                    mma_bf16(acc1[mi][nt2 * 2 + 1], al[mi], bh + 2);
                    mma_bf16(acc1[mi][nt2 * 2],     ah[mi], bl);
                    mma_bf16(acc1[mi][nt2 * 2 + 1], ah[mi], bl + 2);
                }
            }
        }
        __syncthreads();

        if (c + 1 < 32) {
            const int jbN = (c + 1) * 128;
            #pragma unroll
            for (int i = t; i < 3072; i += 512) {
                int arr = i >= 1536;
                int idx = i - arr * 1536;
                int r = idx / 12, c8 = (idx % 12) * 8;
                cp_async16(base + OFF_W1 + (uint32_t)(arr * 26624) + (uint32_t)(r * 104 + c8) * 2,
                           (arr ? gW1l : gW1h) + (size_t)(jbN + r) * 96 + c8);
            }
            const int kcN = (c + 1) * 128;
            const uint32_t bbN = OFF_B2 + (uint32_t)(((c + 1) & 1) * 34816);
            #pragma unroll
            for (int i = t; i < 2048; i += 512) {
                int arr = i >> 10, idx = i & 1023;
                int r = idx >> 4, c8 = (idx & 15) << 3;
                cp_async16(base + bbN + (uint32_t)(arr * 17408) + (uint32_t)(r * 136 + c8) * 2,
                           (arr ? gB2l : gB2h) + (size_t)r * EDIM + kcN + c8);
            }
            CP_COMMIT();
        }

        const uint32_t b2buf = OFF_B2 + (uint32_t)((c & 1) * 34816);
        #pragma unroll
        for (int h = 0; h < 2; h++) {
            if ((wn >> 1) == h) {
                __nv_bfloat16* sSh = (__nv_bfloat16*)(dsm + OFF_SH);
                __nv_bfloat16* sSl = (__nv_bfloat16*)(dsm + OFF_SL);
                #pragma unroll
                for (int mi = 0; mi < 2; mi++)
                    #pragma unroll
                    for (int nt = 0; nt < 4; nt++) {
                        int row = wm * 32 + mi * 16 + g;
                        int ccol = wn * 32 + nt * 8 + i2;
                        int lcol = ccol - h * 64;
                        float bv0 = b1[c * 128 + ccol], bv1 = b1[c * 128 + ccol + 1];
                        float v0 = fmaxf(acc1[mi][nt][0] + bv0, 0.f);
                        float v1 = fmaxf(acc1[mi][nt][1] + bv1, 0.f);
                        float v2 = fmaxf(acc1[mi][nt][2] + bv0, 0.f);
                        float v3 = fmaxf(acc1[mi][nt][3] + bv1, 0.f);
                        __nv_bfloat16 h0, l0, h1, l1;
                        split_bf16(v0, h0, l0); split_bf16(v1, h1, l1);
                        *(uint32_t*)(sSh + row * 72 + lcol) =
                            (uint32_t)__bfloat16_as_ushort(h1) << 16 | __bfloat16_as_ushort(h0);
                        *(uint32_t*)(sSl + row * 72 + lcol) =
                            (uint32_t)__bfloat16_as_ushort(l1) << 16 | __bfloat16_as_ushort(l0);
                        split_bf16(v2, h0, l0); split_bf16(v3, h1, l1);
                        *(uint32_t*)(sSh + (row + 8) * 72 + lcol) =
                            (uint32_t)__bfloat16_as_ushort(h1) << 16 | __bfloat16_as_ushort(h0);
                        *(uint32_t*)(sSl + (row + 8) * 72 + lcol) =
                            (uint32_t)__bfloat16_as_ushort(l1) << 16 | __bfloat16_as_ushort(l0);
                    }
            }
            __syncthreads();
            #pragma unroll
            for (int kk = 0; kk < 4; kk++) {
                uint32_t ah[4], al[4];
                ldsm4(ah, base + stOff + kk * 32);
                ldsm4(al, base + stOff + (OFF_SL - OFF_SH) + kk * 32);
                #pragma unroll
                for (int nt2 = 0; nt2 < 2; nt2++) {
                    uint32_t bh[4], bl[4];
                    uint32_t boff = base + b2buf + b2Off + (uint32_t)(nt2 * 16 * 136 * 2) + (uint32_t)(h * 128) + kk * 32;
                    ldsm4(bh, boff);
                    ldsm4(bl, boff + 17408u);
                    mma_bf16(acc2[nt2 * 2],     ah, bh);
                    mma_bf16(acc2[nt2 * 2 + 1], ah, bh + 2);
                    mma_bf16(acc2[nt2 * 2],     al, bh);
                    mma_bf16(acc2[nt2 * 2 + 1], al, bh + 2);
                    mma_bf16(acc2[nt2 * 2],     ah, bl);
                    mma_bf16(acc2[nt2 * 2 + 1], ah, bl + 2);
                }
            }
            __syncthreads();
        }
    }

    float* stage = (float*)dsm;
    #pragma unroll
    for (int nt = 0; nt < 4; nt++) {
        int row = wm2 * 16 + g;
        int col = wn2 * 32 + nt * 8 + i2;
        stage[row * 68 + col]           = fmaxf(acc2[nt][0] + sBias2[col], 0.f);
        stage[row * 68 + col + 1]       = fmaxf(acc2[nt][1] + sBias2[col + 1], 0.f);
        stage[(row + 8) * 68 + col]     = fmaxf(acc2[nt][2] + sBias2[col], 0.f);
        stage[(row + 8) * 68 + col + 1] = fmaxf(acc2[nt][3] + sBias2[col + 1], 0.f);
    }
    __syncthreads();
    for (int i = t; i < 2048; i += 512) {
        int r = i >> 4, c4 = (i & 15) << 2;
        *(float4*)&g_emb[(size_t)(rb + r) * 64 + c4] = *(float4*)&stage[r * 68 + c4];
    }
}

// ============== k_x (unchanged) ==============
__global__ __launch_bounds__(256) void k_x(const float* __restrict__ wih,
                                           const float* __restrict__ bih,
                                           const float* __restrict__ bhh) {
    extern __shared__ float smx[];
    float* sAT = smx;
    float* sWT = smx + 64 * 68;
    const int t = threadIdx.x;
    const int rb = blockIdx.y * 64;
    const int jb = blockIdx.x * 128;
    #pragma unroll
    for (int i = t; i < 1024; i += 256) {
        int q = i >> 6, r = i & 63;
        float4 v = *reinterpret_cast<const float4*>(&g_emb[(size_t)(rb + r) * 64 + q * 4]);
        sAT[(q * 4 + 0) * 68 + r] = v.x;
        sAT[(q * 4 + 1) * 68 + r] = v.y;
        sAT[(q * 4 + 2) * 68 + r] = v.z;
        sAT[(q * 4 + 3) * 68 + r] = v.w;
    }
    #pragma unroll
    for (int i = t; i < 2048; i += 256) {
        int kq = i >> 7, j = i & 127;
        float4 v = *reinterpret_cast<const float4*>(&wih[(size_t)(jb + j) * 64 + kq * 4]);
        sWT[(kq * 4 + 0) * 128 + j] = v.x;
        sWT[(kq * 4 + 1) * 128 + j] = v.y;
        sWT[(kq * 4 + 2) * 128 + j] = v.z;
        sWT[(kq * 4 + 3) * 128 + j] = v.w;
    }
    __syncthreads();
    const int jj = t & 31, rr = t >> 5;
    const int j = jj * 4, r0 = rr * 8;
    unsigned long long acc[4][4];
    #pragma unroll
    for (int p = 0; p < 4; p++)
        #pragma unroll
        for (int q = 0; q < 4; q++) acc[p][q] = 0ULL;
    #pragma unroll 16
    for (int k = 0; k < 64; k++) {
        const ulonglong2* pa = reinterpret_cast<const ulonglong2*>(sAT + k * 68 + r0);
        ulonglong2 a01 = pa[0], a23 = pa[1];
        unsigned long long a[4] = {a01.x, a01.y, a23.x, a23.y};
        float4 wv = *reinterpret_cast<const float4*>(sWT + k * 128 + j);
        unsigned long long w[4] = {pack2(wv.x), pack2(wv.y), pack2(wv.z), pack2(wv.w)};
        #pragma unroll
        for (int p = 0; p < 4; p++)
            #pragma unroll
            for (int q = 0; q < 4; q++) acc[p][q] = ffma2(a[p], w[q], acc[p][q]);
    }
    float4 bi = *reinterpret_cast<const float4*>(&bih[jb + j]);
    float4 bh = *reinterpret_cast<const float4*>(&bhh[jb + j]);
    float4 bv = make_float4(bi.x + bh.x, bi.y + bh.y, bi.z + bh.z, bi.w + bh.w);
    #pragma unroll
    for (int p = 0; p < 4; p++) {
        float x0, y0, x1, y1, x2, y2, x3, y3;
        unpack2(acc[p][0], x0, y0);
        unpack2(acc[p][1], x1, y1);
        unpack2(acc[p][2], x2, y2);
        unpack2(acc[p][3], x3, y3);
        float4 rA = make_float4(x0 + bv.x, x1 + bv.y, x2 + bv.z, x3 + bv.w);
        float4 rB = make_float4(y0 + bv.x, y1 + bv.y, y2 + bv.z, y3 + bv.w);
        int rowA = rb + r0 + 2 * p;
        int rowB = rowA + 1;
        {
            int branch = rowA >> 13, n = rowA & 8191, b = n >> 9, s = n & 511;
            size_t dst = ((size_t)branch * NF + (size_t)s * 16 + b) * 256 + jb + j;
            *reinterpret_cast<float4*>(&g_X[dst]) = rA;
        }
        {
            int branch = rowB >> 13, n = rowB & 8191, b = n >> 9, s = n & 511;
            size_t dst = ((size_t)branch * NF + (size_t)s * 16 + b) * 256 + jb + j;
            *reinterpret_cast<float4*>(&g_X[dst]) = rB;
        }
    }
}

// ============== k_lstm (warp-specialized pipelined; FIXED barrier count 514==514) ==============
__global__ __launch_bounds__(512) void k_lstm(const float* __restrict__ whh1,
                                              const float* __restrict__ wih2,
                                              const float* __restrict__ whh2,
                                              const float* __restrict__ bih2,
                                              const float* __restrict__ bhh2) {
    __shared__ __align__(16) float sh1[2][64];
    __shared__ __align__(16) float sh2[2][32];
    const int b = blockIdx.x, t = threadIdx.x;

    if (t < 128) sh1[t >> 6][t & 63] = 0.f;
    else if (t < 192) sh2[(t >> 5) & 1][t & 31] = 0.f;

    if (t < 256) {
        // ---------------- layer-1 group (barriers: 1 + 512 + 1 = 514) ----------------
        const int u = t >> 2, q = t & 3;
        const int gi = q * 64 + u;
        const int lanebase = t & 28;
        float w1[64];
        #pragma unroll
        for (int k = 0; k < 64; k++) w1[k] = whh1[gi * 64 + k];
        const float* xbase = g_X + (size_t)b * 256;
        float c1 = 0.f;
        float xg = xbase[gi];
        BAR512();   // B1: init visible

        for (int s = 0; s < 512; s++) {
            float xn = (s < 511) ? xbase[(size_t)(s + 1) * 4096 + gi] : 0.f;
            const float4* h1rd = (const float4*)sh1[(s + 1) & 1];   // h1(s-1)
            float a0 = xg, a1 = 0.f, a2 = 0.f, a3 = 0.f;
            #pragma unroll
            for (int k = 0; k < 16; k++) {
                float4 hv = h1rd[k];
                a0 = fmaf(hv.x, w1[4 * k],     a0);
                a1 = fmaf(hv.y, w1[4 * k + 1], a1);
                a2 = fmaf(hv.z, w1[4 * k + 2], a2);
                a3 = fmaf(hv.w, w1[4 * k + 3], a3);
            }
            float av = (a0 + a1) + (a2 + a3);
            float gv = (q == 2) ? tanh_f(av) : sigf(av);
            float vi = __shfl_sync(0xffffffffu, gv, lanebase);
            float vf = __shfl_sync(0xffffffffu, gv, lanebase + 1);
            float vg = __shfl_sync(0xffffffffu, gv, lanebase + 2);
            float vo = __shfl_sync(0xffffffffu, gv, lanebase + 3);
            if (q == 0) {
                c1 = vf * c1 + vi * vg;
                float h1v = vo * tanh_f(c1);
                sh1[s & 1][u] = h1v;
                g_H1[((size_t)s * 16 + b) * 64 + u] = h1v;
                g_C1[((size_t)s * 16 + b) * 64 + u] = c1;
            }
            xg = xn;
            BAR512();   // B(s+2)
        }
        BAR512();   // B514: pair with L2's final in-loop barrier
    } else {
        // ---------------- layer-2 group (barriers: 2 + 512 = 514) ----------------
        const int tt = t - 256;
        const int v = tt >> 3, q2 = (tt >> 1) & 3, kh = tt & 1;
        const int g2 = q2 * 32 + v;
        const int lane = tt & 31, octbase = lane & 24;
        float w2[48];
        #pragma unroll
        for (int k = 0; k < 48; k++) {
            int kk = kh * 48 + k;
            w2[k] = (kk < 64) ? wih2[g2 * 64 + kk] : whh2[g2 * 32 + (kk - 64)];
        }
        const float b2v = (kh == 0) ? (bih2[g2] + bhh2[g2]) : 0.f;
        float c2 = 0.f;
        BAR512();   // B1
        BAR512();   // B2: h1(0) now visible
        for (int sp = 0; sp < 512; sp++) {
            const float4* h1v4 = (const float4*)sh1[sp & 1];          // h1(sp)
            const float4* h2v4 = (const float4*)sh2[(sp + 1) & 1];    // h2(sp-1)
            float p0 = b2v, p1 = 0.f, p2 = 0.f, p3 = 0.f;
            if (kh == 0) {
                #pragma unroll
                for (int k = 0; k < 12; k++) {
                    float4 hv = h1v4[k];
                    p0 = fmaf(hv.x, w2[4 * k],     p0);
                    p1 = fmaf(hv.y, w2[4 * k + 1], p1);
                    p2 = fmaf(hv.z, w2[4 * k + 2], p2);
                    p3 = fmaf(hv.w, w2[4 * k + 3], p3);
                }
            } else {
                #pragma unroll
                for (int k = 0; k < 4; k++) {
                    float4 hv = h1v4[12 + k];
                    p0 = fmaf(hv.x, w2[4 * k],     p0);
                    p1 = fmaf(hv.y, w2[4 * k + 1], p1);
                    p2 = fmaf(hv.z, w2[4 * k + 2], p2);
                    p3 = fmaf(hv.w, w2[4 * k + 3], p3);
                }
                #pragma unroll
                for (int k = 0; k < 8; k++) {
                    float4 hv = h2v4[k];
                    p0 = fmaf(hv.x, w2[16 + 4 * k],     p0);
                    p1 = fmaf(hv.y, w2[16 + 4 * k + 1], p1);
                    p2 = fmaf(hv.z, w2[16 + 4 * k + 2], p2);
                    p3 = fmaf(hv.w, w2[16 + 4 * k + 3], p3);
                }
            }
            float part = (p0 + p1) + (p2 + p3);
            float pv = part + __shfl_xor_sync(0xffffffffu, part, 1);
            float gv = (q2 == 2) ? tanh_f(pv) : sigf(pv);
            float vi = __shfl_sync(0xffffffffu, gv, octbase);
            float vf = __shfl_sync(0xffffffffu, gv, octbase + 2);
            float vg = __shfl_sync(0xffffffffu, gv, octbase + 4);
            float vo = __shfl_sync(0xffffffffu, gv, octbase + 6);
            if ((tt & 7) == 0) {
                c2 = vf * c2 + vi * vg;
                float h2v = vo * tanh_f(c2);
                sh2[sp & 1][v] = h2v;
                g_H2[((size_t)sp * 16 + b) * 32 + v] = h2v;
                g_C2[((size_t)sp * 16 + b) * 32 + v] = c2;
            }
            BAR512();   // B(sp+3)
        }
    }
}

// ============== k_f (unchanged) ==============
__global__ __launch_bounds__(256) void k_f(const float* __restrict__ whh1,
                                           const float* __restrict__ wih2,
                                           const float* __restrict__ whh2,
                                           const float* __restrict__ bih2,
                                           const float* __restrict__ bhh2,
                                           const float* __restrict__ fc8w,
                                           const float* __restrict__ fc8b,
                                           float* __restrict__ out_prog,
                                           float* __restrict__ out_fprog) {
    extern __shared__ float smf[];
    float* w1T  = smf;
    float* wi2T = w1T + 64 * 256;
    float* wh2T = wi2T + 64 * 128;
    float* b2s  = wh2T + 32 * 128;
    float* sH1  = b2s + 128;
    float* sC1  = sH1 + 1024;
    float* sH2  = sC1 + 1024;
    float* sC2  = sH2 + 512;
    float* sG1  = sC2 + 512;
    float* sFh1 = sG1 + 4096;
    float* sG2  = sFh1 + 1024;
    float* sFh2 = sG2 + 2048;
    const int t = threadIdx.x;
    const int s = blockIdx.x;
    const size_t r0 = (size_t)s * 16;
    for (int i = t; i < 64 * 256; i += 256) {
        int k = i >> 8, g = i & 255;
        w1T[i] = whh1[g * 64 + k];
    }
    for (int i = t; i < 64 * 128; i += 256) {
        int k = i >> 7, g = i & 127;
        wi2T[i] = wih2[g * 64 + k];
    }
    for (int i = t; i < 32 * 128; i += 256) {
        int k = i >> 7, g = i & 127;
        wh2T[i] = whh2[g * 32 + k];
    }
    if (t < 128) b2s[t] = bih2[t] + bhh2[t];
    for (int i = t; i < 1024; i += 256) sH1[i] = g_H1[r0 * 64 + i];
    for (int i = t; i < 1024; i += 256) sC1[i] = g_C1[r0 * 64 + i];
    for (int i = t; i < 512;  i += 256) sH2[i] = g_H2[r0 * 32 + i];
    for (int i = t; i < 512;  i += 256) sC2[i] = g_C2[r0 * 32 + i];
    for (int i = t; i < 4096; i += 256) sG1[i] = g_X[(size_t)NF * 256 + r0 * 256 + i];
    __syncthreads();
    {
        float acc[16];
        #pragma unroll
        for (int r = 0; r < 16; r++) acc[r] = sG1[r * 256 + t];
        #pragma unroll 8
        for (int k = 0; k < 64; k++) {
            float w = w1T[k * 256 + t];
            #pragma unroll
            for (int r = 0; r < 16; r++) acc[r] = fmaf(sH1[r * 64 + k], w, acc[r]);
        }
        bool is_g = ((t >> 6) == 2);
        #pragma unroll
        for (int r = 0; r < 16; r++)
            sG1[r * 256 + t] = is_g ? tanhf(acc[r]) : sigf(acc[r]);
    }
    __syncthreads();
    for (int i = t; i < 1024; i += 256) {
        int r = i >> 6, u = i & 63;
        const float* g = sG1 + r * 256;
        float c = g[64 + u] * sC1[r * 64 + u] + g[u] * g[128 + u];
        sFh1[r * 64 + u] = g[192 + u] * tanhf(c);
    }
    __syncthreads();
    if (t < 128) {
        float acc[16];
        #pragma unroll
        for (int r = 0; r < 16; r++) acc[r] = b2s[t];
        #pragma unroll 8
        for (int k = 0; k < 64; k++) {
            float w = wi2T[k * 128 + t];
            #pragma unroll
            for (int r = 0; r < 16; r++) acc[r] = fmaf(sFh1[r * 64 + k], w, acc[r]);
        }
        #pragma unroll 8
        for (int k = 0; k < 32; k++) {
            float w = wh2T[k * 128 + t];
            #pragma unroll
            for (int r = 0; r < 16; r++) acc[r] = fmaf(sH2[r * 32 + k], w, acc[r]);
        }
        bool is_g = ((t >> 5) == 2);
        #pragma unroll
        for (int r = 0; r < 16; r++)
            sG2[r * 128 + t] = is_g ? tanhf(acc[r]) : sigf(acc[r]);
    }
    __syncthreads();
    for (int i = t; i < 512; i += 256) {
        int r = i >> 5, u = i & 31;
        const float* g = sG2 + r * 128;
        float c = g[32 + u] * sC2[r * 32 + u] + g[u] * g[64 + u];
        sFh2[r * 32 + u] = g[96 + u] * tanhf(c);
    }
    __syncthreads();
    if (t < 32) {
        int r = t >> 1, which = t & 1;
        const float* v = which ? (sFh2 + r * 32) : (sH2 + r * 32);
        float acc = fc8b[0];
        #pragma unroll
        for (int k = 0; k < 32; k++) acc = fmaf(v[k], fc8w[k], acc);
        float ov = sigf(acc);
        int b = r;
        if (which) out_fprog[(size_t)b * 512 + s] = ov;
        else       out_prog[(size_t)b * 512 + s] = ov;
    }
}

// =====================================================================
extern "C" void kernel_launch(void* const* d_in, const int* in_sizes, int n_in,
                              void* d_out, int out_size) {
    const float* frames  = (const float*)d_in[0];
    const float* spp_w   = (const float*)d_in[1];
    const float* spp_b   = (const float*)d_in[2];
    const float* fore_w  = (const float*)d_in[3];
    const float* fore_b  = (const float*)d_in[4];
    const float* fc7_w   = (const float*)d_in[5];
    const float* fc7_b   = (const float*)d_in[6];
    const float* l1_wih  = (const float*)d_in[7];
    const float* l1_whh  = (const float*)d_in[8];
    const float* l1_bih  = (const float*)d_in[9];
    const float* l1_bhh  = (const float*)d_in[10];
    const float* l2_wih  = (const float*)d_in[11];
    const float* l2_whh  = (const float*)d_in[12];
    const float* l2_bih  = (const float*)d_in[13];
    const float* l2_bhh  = (const float*)d_in[14];
    const float* fc8_w   = (const float*)d_in[15];
    const float* fc8_b   = (const float*)d_in[16];

    float* out         = (float*)d_out;
    float* out_prog    = out;
    float* out_fprog   = out + 8192;
    float* out_pooled  = out + 16384;
    float* out_fpooled = out + 16384 + 737280;

    const int smem_x = (64 * 68 + 64 * 128) * 4;
    const int smem_f = (64 * 256 + 64 * 128 + 32 * 128 + 128 +
                        1024 + 1024 + 512 + 512 + 4096 + 1024 + 2048 + 512) * 4;
    cudaFuncSetAttribute(k_mlp, cudaFuncAttributeMaxDynamicSharedMemorySize, MLP_SMEM);
    cudaFuncSetAttribute(k_x,   cudaFuncAttributeMaxDynamicSharedMemorySize, smem_x);
    cudaFuncSetAttribute(k_f,   cudaFuncAttributeMaxDynamicSharedMemorySize, smem_f);

    k_spp<<<NF, 256>>>(frames, fore_w, fore_b, out_pooled, out_fpooled);
    k_prepW1<<<EDIM / 8, 256>>>(spp_w);
    k_prepB2<<<64, 256>>>(fc7_w);
    k_mlp<<<128, 512, MLP_SMEM>>>(spp_b, fc7_b);
    k_x<<<dim3(2, 256), 256, smem_x>>>(l1_wih, l1_bih, l1_bhh);
    k_lstm<<<16, 512>>>(l1_whh, l2_wih, l2_whh, l2_bih, l2_bhh);
    k_f<<<512, 256, smem_f>>>(l1_whh, l2_wih, l2_whh, l2_bih, l2_bhh, fc8_w, fc8_b,
                              out_prog, out_fprog);
}

// round 16
// speedup vs baseline: 1.1074x; 1.0002x over previous
#include <cuda_runtime.h>
#include <cuda_bf16.h>
#include <cstdint>

#define NF    8192
#define NROWS 16384
#define EDIM  4096

__device__ float g_emb[NROWS * 64];
__device__ float g_X[2 * NF * 256];
__device__ float g_H1[512 * 16 * 64];
__device__ float g_C1[512 * 16 * 64];
__device__ float g_H2[512 * 16 * 32];
__device__ float g_C2[512 * 16 * 32];
__device__ __nv_bfloat16 gA1h[(size_t)NROWS * 96];
__device__ __nv_bfloat16 gA1l[(size_t)NROWS * 96];
__device__ __nv_bfloat16 gW1h[(size_t)EDIM * 96];
__device__ __nv_bfloat16 gW1l[(size_t)EDIM * 96];
__device__ __nv_bfloat16 gB2h[64 * EDIM];
__device__ __nv_bfloat16 gB2l[64 * EDIM];

__device__ __forceinline__ uint32_t smem_to_u32(const void* p) {
    uint32_t a;
    asm("{ .reg .u64 t; cvta.to.shared.u64 t, %1; cvt.u32.u64 %0, t; }" : "=r"(a) : "l"(p));
    return a;
}
__device__ __forceinline__ void ldsm4(uint32_t* r, uint32_t addr) {
    asm volatile("ldmatrix.sync.aligned.m8n8.x4.shared.b16 {%0,%1,%2,%3}, [%4];"
                 : "=r"(r[0]), "=r"(r[1]), "=r"(r[2]), "=r"(r[3]) : "r"(addr));
}
__device__ __forceinline__ void mma_bf16(float* d, const uint32_t* a, const uint32_t* b) {
    asm volatile("mma.sync.aligned.m16n8k16.row.col.f32.bf16.bf16.f32 "
                 "{%0,%1,%2,%3}, {%4,%5,%6,%7}, {%8,%9}, {%0,%1,%2,%3};"
                 : "+f"(d[0]), "+f"(d[1]), "+f"(d[2]), "+f"(d[3])
                 : "r"(a[0]), "r"(a[1]), "r"(a[2]), "r"(a[3]), "r"(b[0]), "r"(b[1]));
}
__device__ __forceinline__ void cp_async16(uint32_t saddr, const void* g) {
    asm volatile("cp.async.cg.shared.global [%0], [%1], 16;" :: "r"(saddr), "l"(g));
}
#define CP_COMMIT() asm volatile("cp.async.commit_group;" ::: "memory")
#define CP_WAIT0()  asm volatile("cp.async.wait_group 0;" ::: "memory")
#define BAR512()    asm volatile("bar.sync 0, 512;" ::: "memory")
__device__ __forceinline__ unsigned long long ffma2(unsigned long long a, unsigned long long b, unsigned long long c) {
    unsigned long long d;
    asm("fma.rn.f32x2 %0, %1, %2, %3;" : "=l"(d) : "l"(a), "l"(b), "l"(c));
    return d;
}
__device__ __forceinline__ unsigned long long pack2(float x) {
    unsigned long long d;
    unsigned int u = __float_as_uint(x);
    asm("mov.b64 %0, {%1, %1};" : "=l"(d) : "r"(u));
    return d;
}
__device__ __forceinline__ void unpack2(unsigned long long v, float& lo, float& hi) {
    unsigned int a, b;
    asm("mov.b64 {%0, %1}, %2;" : "=r"(a), "=r"(b) : "l"(v));
    lo = __uint_as_float(a);
    hi = __uint_as_float(b);
}
__device__ __forceinline__ float sigf(float x) { return 1.0f / (1.0f + __expf(-x)); }
__device__ __forceinline__ float tanh_f(float x) { return 1.0f - 2.0f / (__expf(2.0f * x) + 1.0f); }
__device__ __forceinline__ void split_bf16(float x, __nv_bfloat16& h, __nv_bfloat16& l) {
    h = __float2bfloat16(x);
    l = __float2bfloat16(x - __bfloat162float(h));
}

// ============== k_spp (Wf staged in smem, transposed; dynamic smem) ==============
// dyn smem layout (floats): sF[6912] | sW[8100] | sL4[48] | sP[90] -> 60600 floats? no:
// 6912 + 8100 + 48 + 90 = 15150 floats = 60600 B
#define SPP_SMEM (15152 * 4)
__global__ __launch_bounds__(256) void k_spp(const float* __restrict__ frames,
                                             const float* __restrict__ Wf,
                                             const float* __restrict__ bf,
                                             float* __restrict__ out_pooled,
                                             float* __restrict__ out_fpooled) {
    extern __shared__ __align__(16) float sdyn[];
    float* sF  = sdyn;            // [6912]
    float* sW  = sdyn + 6912;     // [90][90] transposed: sW[k*90+j] = Wf[j][k]
    float* sL4 = sdyn + 15012;    // [48]
    float* sP  = sdyn + 15060;    // [90]
    const int n = blockIdx.x, t = threadIdx.x;
    const float4* src = reinterpret_cast<const float4*>(frames + (size_t)n * 6912);
    float4* dst = reinterpret_cast<float4*>(sF);
    #pragma unroll
    for (int i = t; i < 1728; i += 256) dst[i] = src[i];
    // stage Wf transposed (coalesced gmem read, scattered smem write)
    for (int i = t; i < 8100; i += 256) {
        int j = i / 90, k = i - j * 90;
        sW[k * 90 + j] = Wf[i];
    }
    __syncthreads();
    {
        int og = t >> 2, sub = t & 3;
        bool act = (og < 48);
        float m = -1e30f;
        if (act) {
            int c = og >> 4, rem = og & 15, i = rem >> 2, j = rem & 3;
            const float* base = sF + c * 2304 + (i * 12 + sub * 3) * 48 + j * 12;
            #pragma unroll
            for (int r = 0; r < 3; r++)
                #pragma unroll
                for (int q = 0; q < 12; q++) m = fmaxf(m, base[r * 48 + q]);
        }
        m = fmaxf(m, __shfl_xor_sync(0xffffffffu, m, 1));
        m = fmaxf(m, __shfl_xor_sync(0xffffffffu, m, 2));
        if (act && sub == 0) { sL4[og] = m; sP[og] = m; }
    }
    {
        int og = t >> 3, sub = t & 7;
        bool act = (og < 27);
        float m = -1e30f;
        if (act) {
            int c = og / 9, rem = og % 9, i = rem / 3, j = rem % 3;
            const float* base = sF + c * 2304 + (i * 16 + sub * 2) * 48 + j * 16;
            #pragma unroll
            for (int r = 0; r < 2; r++)
                #pragma unroll
                for (int q = 0; q < 16; q++) m = fmaxf(m, base[r * 48 + q]);
        }
        m = fmaxf(m, __shfl_xor_sync(0xffffffffu, m, 1));
        m = fmaxf(m, __shfl_xor_sync(0xffffffffu, m, 2));
        m = fmaxf(m, __shfl_xor_sync(0xffffffffu, m, 4));
        if (act && sub == 0) sP[48 + og] = m;
    }
    __syncthreads();
    if (t < 12) {
        int c = t >> 2, rem = t & 3, i = rem >> 1, j = rem & 1;
        const float* L = sL4 + c * 16;
        float m = fmaxf(fmaxf(L[(2 * i) * 4 + 2 * j], L[(2 * i) * 4 + 2 * j + 1]),
                        fmaxf(L[(2 * i + 1) * 4 + 2 * j], L[(2 * i + 1) * 4 + 2 * j + 1]));
        sP[75 + t] = m;
    } else if (t < 15) {
        int c = t - 12;
        float m = -1e30f;
        #pragma unroll
        for (int q = 0; q < 16; q++) m = fmaxf(m, sL4[c * 16 + q]);
        sP[87 + c] = m;
    }
    __syncthreads();
    if (t < 90) {
        float v = sP[t];
        out_pooled[(size_t)n * 90 + t] = v;
        float a0 = bf[t], a1 = 0.f;
        #pragma unroll
        for (int k = 0; k < 90; k += 2) {
            a0 = fmaf(sP[k], sW[k * 90 + t], a0);
            a1 = fmaf(sP[k + 1], sW[(k + 1) * 90 + t], a1);
        }
        float acc = a0 + a1;
        out_fpooled[(size_t)n * 90 + t] = acc;
        __nv_bfloat16 h, l;
        split_bf16(v, h, l);
        gA1h[(size_t)n * 96 + t] = h;
        gA1l[(size_t)n * 96 + t] = l;
        split_bf16(acc, h, l);
        gA1h[(size_t)(NF + n) * 96 + t] = h;
        gA1l[(size_t)(NF + n) * 96 + t] = l;
    } else if (t < 96) {
        __nv_bfloat16 z = __float2bfloat16(0.f);
        gA1h[(size_t)n * 96 + t] = z;
        gA1l[(size_t)n * 96 + t] = z;
        gA1h[(size_t)(NF + n) * 96 + t] = z;
        gA1l[(size_t)(NF + n) * 96 + t] = z;
    }
}

// ============== prep kernels ==============
__global__ __launch_bounds__(256) void k_prepW1(const float* __restrict__ W1) {
    int r = blockIdx.x * 8 + (threadIdx.x >> 5);
    int lane = threadIdx.x & 31;
    const float* src = W1 + (size_t)r * 90;
    #pragma unroll
    for (int it = 0; it < 3; it++) {
        int k = it * 32 + lane;
        float x = (k < 90) ? src[k] : 0.f;
        __nv_bfloat16 h, l;
        split_bf16(x, h, l);
        gW1h[(size_t)r * 96 + k] = h;
        gW1l[(size_t)r * 96 + k] = l;
    }
}
__global__ __launch_bounds__(256) void k_prepB2(const float* __restrict__ F) {
    for (int i = blockIdx.x * 256 + threadIdx.x; i < 64 * EDIM; i += gridDim.x * 256) {
        __nv_bfloat16 h, l;
        split_bf16(F[i], h, l);
        gB2h[i] = h;
        gB2l[i] = l;
    }
}

// ============== FUSED MLP (unchanged) ==============
#define MLP_SMEM 212992
#define OFF_A1 0u
#define OFF_W1 53248u
#define OFF_SH 106496u
#define OFF_SL 124928u
#define OFF_B2 143360u
__global__ __launch_bounds__(512) void k_mlp(const float* __restrict__ b1,
                                             const float* __restrict__ b7) {
    extern __shared__ __align__(16) char dsm[];
    __shared__ float sBias2[64];
    const int t = threadIdx.x, lane = t & 31, wid = t >> 5;
    const int rb = blockIdx.x * 128;
    const uint32_t base = smem_to_u32(dsm);
    if (t < 64) sBias2[t] = b7[t];

    #pragma unroll
    for (int i = t; i < 3072; i += 512) {
        int arr = i >= 1536;
        int idx = i - arr * 1536;
        int r = idx / 12, c8 = (idx % 12) * 8;
        cp_async16(base + OFF_A1 + (uint32_t)(arr * 26624) + (uint32_t)(r * 104 + c8) * 2,
                   (arr ? gA1l : gA1h) + (size_t)(rb + r) * 96 + c8);
        cp_async16(base + OFF_W1 + (uint32_t)(arr * 26624) + (uint32_t)(r * 104 + c8) * 2,
                   (arr ? gW1l : gW1h) + (size_t)r * 96 + c8);
    }
    #pragma unroll
    for (int i = t; i < 2048; i += 512) {
        int arr = i >> 10, idx = i & 1023;
        int r = idx >> 4, c8 = (idx & 15) << 3;
        cp_async16(base + OFF_B2 + (uint32_t)(arr * 17408) + (uint32_t)(r * 136 + c8) * 2,
                   (arr ? gB2l : gB2h) + (size_t)r * EDIM + c8);
    }
    CP_COMMIT();

    const int wm = wid >> 2, wn = wid & 3;
    const int wm2 = wid >> 1, wn2 = wid & 1;
    const int j = lane >> 3;
    const uint32_t a1Off = OFF_A1 + (uint32_t)((wm * 32 + (lane & 15)) * 104 + ((lane >> 4) << 3)) * 2;
    const uint32_t w1Off = OFF_W1 + (uint32_t)((wn * 32 + ((j >> 1) << 3) + (lane & 7)) * 104 + ((j & 1) << 3)) * 2;
    const uint32_t stOff = OFF_SH + (uint32_t)((wm2 * 16 + (lane & 15)) * 72 + ((lane >> 4) << 3)) * 2;
    const uint32_t b2Off = (uint32_t)((wn2 * 32 + ((j >> 1) << 3) + (lane & 7)) * 136 + ((j & 1) << 3)) * 2;

    float acc2[4][4];
    #pragma unroll
    for (int nt = 0; nt < 4; nt++)
        #pragma unroll
        for (int q = 0; q < 4; q++) acc2[nt][q] = 0.f;

    const int g = lane >> 2, i2 = (lane & 3) * 2;

    for (int c = 0; c < 32; c++) {
        CP_WAIT0();
        __syncthreads();

        float acc1[2][4][4];
        #pragma unroll
        for (int mi = 0; mi < 2; mi++)
            #pragma unroll
            for (int nt = 0; nt < 4; nt++)
                #pragma unroll
                for (int q = 0; q < 4; q++) acc1[mi][nt][q] = 0.f;
        #pragma unroll
        for (int kk = 0; kk < 6; kk++) {
            uint32_t ah[2][4], al[2][4];
            ldsm4(ah[0], base + a1Off + kk * 32);
            ldsm4(ah[1], base + a1Off + (16 * 104 * 2) + kk * 32);
            ldsm4(al[0], base + a1Off + 26624u + kk * 32);
            ldsm4(al[1], base + a1Off + 26624u + (16 * 104 * 2) + kk * 32);
            #pragma unroll
            for (int nt2 = 0; nt2 < 2; nt2++) {
                uint32_t bh[4], bl[4];
                ldsm4(bh, base + w1Off + (uint32_t)(nt2 * 16 * 104 * 2) + kk * 32);
                ldsm4(bl, base + w1Off + 26624u + (uint32_t)(nt2 * 16 * 104 * 2) + kk * 32);
                #pragma unroll
                for (int mi = 0; mi < 2; mi++) {
                    mma_bf16(acc1[mi][nt2 * 2],     ah[mi], bh);
                    mma_bf16(acc1[mi][nt2 * 2 + 1], ah[mi], bh + 2);
                    mma_bf16(acc1[mi][nt2 * 2],     al[mi], bh);
                    mma_bf16(acc1[mi][nt2 * 2 + 1], al[mi], bh + 2);
                    mma_bf16(acc1[mi][nt2 * 2],     ah[mi], bl);
                    mma_bf16(acc1[mi][nt2 * 2 + 1], ah[mi], bl + 2);
                }
            }
        }
        __syncthreads();

        if (c + 1 < 32) {
            const int jbN = (c + 1) * 128;
            #pragma unroll
            for (int i = t; i < 3072; i += 512) {
                int arr = i >= 1536;
                int idx = i - arr * 1536;
                int r = idx / 12, c8 = (idx % 12) * 8;
                cp_async16(base + OFF_W1 + (uint32_t)(arr * 26624) + (uint32_t)(r * 104 + c8) * 2,
                           (arr ? gW1l : gW1h) + (size_t)(jbN + r) * 96 + c8);
            }
            const int kcN = (c + 1) * 128;
            const uint32_t bbN = OFF_B2 + (uint32_t)(((c + 1) & 1) * 34816);
            #pragma unroll
            for (int i = t; i < 2048; i += 512) {
                int arr = i >> 10, idx = i & 1023;
                int r = idx >> 4, c8 = (idx & 15) << 3;
                cp_async16(base + bbN + (uint32_t)(arr * 17408) + (uint32_t)(r * 136 + c8) * 2,
                           (arr ? gB2l : gB2h) + (size_t)r * EDIM + kcN + c8);
            }
            CP_COMMIT();
        }

        const uint32_t b2buf = OFF_B2 + (uint32_t)((c & 1) * 34816);
        #pragma unroll
        for (int h = 0; h < 2; h++) {
            if ((wn >> 1) == h) {
                __nv_bfloat16* sSh = (__nv_bfloat16*)(dsm + OFF_SH);
                __nv_bfloat16* sSl = (__nv_bfloat16*)(dsm + OFF_SL);
                #pragma unroll
                for (int mi = 0; mi < 2; mi++)
                    #pragma unroll
                    for (int nt = 0; nt < 4; nt++) {
                        int row = wm * 32 + mi * 16 + g;
                        int ccol = wn * 32 + nt * 8 + i2;
                        int lcol = ccol - h * 64;
                        float bv0 = b1[c * 128 + ccol], bv1 = b1[c * 128 + ccol + 1];
                        float v0 = fmaxf(acc1[mi][nt][0] + bv0, 0.f);
                        float v1 = fmaxf(acc1[mi][nt][1] + bv1, 0.f);
                        float v2 = fmaxf(acc1[mi][nt][2] + bv0, 0.f);
                        float v3 = fmaxf(acc1[mi][nt][3] + bv1, 0.f);
                        __nv_bfloat16 h0, l0, h1, l1;
                        split_bf16(v0, h0, l0); split_bf16(v1, h1, l1);
                        *(uint32_t*)(sSh + row * 72 + lcol) =
                            (uint32_t)__bfloat16_as_ushort(h1) << 16 | __bfloat16_as_ushort(h0);
                        *(uint32_t*)(sSl + row * 72 + lcol) =
                            (uint32_t)__bfloat16_as_ushort(l1) << 16 | __bfloat16_as_ushort(l0);
                        split_bf16(v2, h0, l0); split_bf16(v3, h1, l1);
                        *(uint32_t*)(sSh + (row + 8) * 72 + lcol) =
                            (uint32_t)__bfloat16_as_ushort(h1) << 16 | __bfloat16_as_ushort(h0);
                        *(uint32_t*)(sSl + (row + 8) * 72 + lcol) =
                            (uint32_t)__bfloat16_as_ushort(l1) << 16 | __bfloat16_as_ushort(l0);
                    }
            }
            __syncthreads();
            #pragma unroll
            for (int kk = 0; kk < 4; kk++) {
                uint32_t ah[4], al[4];
                ldsm4(ah, base + stOff + kk * 32);
                ldsm4(al, base + stOff + (OFF_SL - OFF_SH) + kk * 32);
                #pragma unroll
                for (int nt2 = 0; nt2 < 2; nt2++) {
                    uint32_t bh[4], bl[4];
                    uint32_t boff = base + b2buf + b2Off + (uint32_t)(nt2 * 16 * 136 * 2) + (uint32_t)(h * 128) + kk * 32;
                    ldsm4(bh, boff);
                    ldsm4(bl, boff + 17408u);
                    mma_bf16(acc2[nt2 * 2],     ah, bh);
                    mma_bf16(acc2[nt2 * 2 + 1], ah, bh + 2);
                    mma_bf16(acc2[nt2 * 2],     al, bh);
                    mma_bf16(acc2[nt2 * 2 + 1], al, bh + 2);
                    mma_bf16(acc2[nt2 * 2],     ah, bl);
                    mma_bf16(acc2[nt2 * 2 + 1], ah, bl + 2);
                }
            }
            __syncthreads();
        }
    }

    float* stage = (float*)dsm;
    #pragma unroll
    for (int nt = 0; nt < 4; nt++) {
        int row = wm2 * 16 + g;
        int col = wn2 * 32 + nt * 8 + i2;
        stage[row * 68 + col]           = fmaxf(acc2[nt][0] + sBias2[col], 0.f);
        stage[row * 68 + col + 1]       = fmaxf(acc2[nt][1] + sBias2[col + 1], 0.f);
        stage[(row + 8) * 68 + col]     = fmaxf(acc2[nt][2] + sBias2[col], 0.f);
        stage[(row + 8) * 68 + col + 1] = fmaxf(acc2[nt][3] + sBias2[col + 1], 0.f);
    }
    __syncthreads();
    for (int i = t; i < 2048; i += 512) {
        int r = i >> 4, c4 = (i & 15) << 2;
        *(float4*)&g_emb[(size_t)(rb + r) * 64 + c4] = *(float4*)&stage[r * 68 + c4];
    }
}

// ============== k_x (unchanged) ==============
__global__ __launch_bounds__(256) void k_x(const float* __restrict__ wih,
                                           const float* __restrict__ bih,
                                           const float* __restrict__ bhh) {
    extern __shared__ float smx[];
    float* sAT = smx;
    float* sWT = smx + 64 * 68;
    const int t = threadIdx.x;
    const int rb = blockIdx.y * 64;
    const int jb = blockIdx.x * 128;
    #pragma unroll
    for (int i = t; i < 1024; i += 256) {
        int q = i >> 6, r = i & 63;
        float4 v = *reinterpret_cast<const float4*>(&g_emb[(size_t)(rb + r) * 64 + q * 4]);
        sAT[(q * 4 + 0) * 68 + r] = v.x;
        sAT[(q * 4 + 1) * 68 + r] = v.y;
        sAT[(q * 4 + 2) * 68 + r] = v.z;
        sAT[(q * 4 + 3) * 68 + r] = v.w;
    }
    #pragma unroll
    for (int i = t; i < 2048; i += 256) {
        int kq = i >> 7, j = i & 127;
        float4 v = *reinterpret_cast<const float4*>(&wih[(size_t)(jb + j) * 64 + kq * 4]);
        sWT[(kq * 4 + 0) * 128 + j] = v.x;
        sWT[(kq * 4 + 1) * 128 + j] = v.y;
        sWT[(kq * 4 + 2) * 128 + j] = v.z;
        sWT[(kq * 4 + 3) * 128 + j] = v.w;
    }
    __syncthreads();
    const int jj = t & 31, rr = t >> 5;
    const int j = jj * 4, r0 = rr * 8;
    unsigned long long acc[4][4];
    #pragma unroll
    for (int p = 0; p < 4; p++)
        #pragma unroll
        for (int q = 0; q < 4; q++) acc[p][q] = 0ULL;
    #pragma unroll 16
    for (int k = 0; k < 64; k++) {
        const ulonglong2* pa = reinterpret_cast<const ulonglong2*>(sAT + k * 68 + r0);
        ulonglong2 a01 = pa[0], a23 = pa[1];
        unsigned long long a[4] = {a01.x, a01.y, a23.x, a23.y};
        float4 wv = *reinterpret_cast<const float4*>(sWT + k * 128 + j);
        unsigned long long w[4] = {pack2(wv.x), pack2(wv.y), pack2(wv.z), pack2(wv.w)};
        #pragma unroll
        for (int p = 0; p < 4; p++)
            #pragma unroll
            for (int q = 0; q < 4; q++) acc[p][q] = ffma2(a[p], w[q], acc[p][q]);
    }
    float4 bi = *reinterpret_cast<const float4*>(&bih[jb + j]);
    float4 bh = *reinterpret_cast<const float4*>(&bhh[jb + j]);
    float4 bv = make_float4(bi.x + bh.x, bi.y + bh.y, bi.z + bh.z, bi.w + bh.w);
    #pragma unroll
    for (int p = 0; p < 4; p++) {
        float x0, y0, x1, y1, x2, y2, x3, y3;
        unpack2(acc[p][0], x0, y0);
        unpack2(acc[p][1], x1, y1);
        unpack2(acc[p][2], x2, y2);
        unpack2(acc[p][3], x3, y3);
        float4 rA = make_float4(x0 + bv.x, x1 + bv.y, x2 + bv.z, x3 + bv.w);
        float4 rB = make_float4(y0 + bv.x, y1 + bv.y, y2 + bv.z, y3 + bv.w);
        int rowA = rb + r0 + 2 * p;
        int rowB = rowA + 1;
        {
            int branch = rowA >> 13, n = rowA & 8191, b = n >> 9, s = n & 511;
            size_t dst = ((size_t)branch * NF + (size_t)s * 16 + b) * 256 + jb + j;
            *reinterpret_cast<float4*>(&g_X[dst]) = rA;
        }
        {
            int branch = rowB >> 13, n = rowB & 8191, b = n >> 9, s = n & 511;
            size_t dst = ((size_t)branch * NF + (size_t)s * 16 + b) * 256 + jb + j;
            *reinterpret_cast<float4*>(&g_X[dst]) = rB;
        }
    }
}

// ============== k_lstm (unchanged from R15) ==============
__global__ __launch_bounds__(512) void k_lstm(const float* __restrict__ whh1,
                                              const float* __restrict__ wih2,
                                              const float* __restrict__ whh2,
                                              const float* __restrict__ bih2,
                                              const float* __restrict__ bhh2) {
    __shared__ __align__(16) float sh1[2][64];
    __shared__ __align__(16) float sh2[2][32];
    const int b = blockIdx.x, t = threadIdx.x;

    if (t < 128) sh1[t >> 6][t & 63] = 0.f;
    else if (t < 192) sh2[(t >> 5) & 1][t & 31] = 0.f;

    if (t < 256) {
        const int u = t >> 2, q = t & 3;
        const int gi = q * 64 + u;
        const int lanebase = t & 28;
        float w1[64];
        #pragma unroll
        for (int k = 0; k < 64; k++) w1[k] = whh1[gi * 64 + k];
        const float* xbase = g_X + (size_t)b * 256;
        float c1 = 0.f;
        float xg = xbase[gi];
        BAR512();

        for (int s = 0; s < 512; s++) {
            float xn = (s < 511) ? xbase[(size_t)(s + 1) * 4096 + gi] : 0.f;
            const float4* h1rd = (const float4*)sh1[(s + 1) & 1];
            float a0 = xg, a1 = 0.f, a2 = 0.f, a3 = 0.f;
            #pragma unroll
            for (int k = 0; k < 16; k++) {
                float4 hv = h1rd[k];
                a0 = fmaf(hv.x, w1[4 * k],     a0);
                a1 = fmaf(hv.y, w1[4 * k + 1], a1);
                a2 = fmaf(hv.z, w1[4 * k + 2], a2);
                a3 = fmaf(hv.w, w1[4 * k + 3], a3);
            }
            float av = (a0 + a1) + (a2 + a3);
            float gv = (q == 2) ? tanh_f(av) : sigf(av);
            float vi = __shfl_sync(0xffffffffu, gv, lanebase);
            float vf = __shfl_sync(0xffffffffu, gv, lanebase + 1);
            float vg = __shfl_sync(0xffffffffu, gv, lanebase + 2);
            float vo = __shfl_sync(0xffffffffu, gv, lanebase + 3);
            if (q == 0) {
                c1 = vf * c1 + vi * vg;
                float h1v = vo * tanh_f(c1);
                sh1[s & 1][u] = h1v;
                g_H1[((size_t)s * 16 + b) * 64 + u] = h1v;
                g_C1[((size_t)s * 16 + b) * 64 + u] = c1;
            }
            xg = xn;
            BAR512();
        }
        BAR512();
    } else {
        const int tt = t - 256;
        const int v = tt >> 3, q2 = (tt >> 1) & 3, kh = tt & 1;
        const int g2 = q2 * 32 + v;
        const int lane = tt & 31, octbase = lane & 24;
        float w2[48];
        #pragma unroll
        for (int k = 0; k < 48; k++) {
            int kk = kh * 48 + k;
            w2[k] = (kk < 64) ? wih2[g2 * 64 + kk] : whh2[g2 * 32 + (kk - 64)];
        }
        const float b2v = (kh == 0) ? (bih2[g2] + bhh2[g2]) : 0.f;
        float c2 = 0.f;
        BAR512();
        BAR512();
        for (int sp = 0; sp < 512; sp++) {
            const float4* h1v4 = (const float4*)sh1[sp & 1];
            const float4* h2v4 = (const float4*)sh2[(sp + 1) & 1];
            float p0 = b2v, p1 = 0.f, p2 = 0.f, p3 = 0.f;
            if (kh == 0) {
                #pragma unroll
                for (int k = 0; k < 12; k++) {
                    float4 hv = h1v4[k];
                    p0 = fmaf(hv.x, w2[4 * k],     p0);
                    p1 = fmaf(hv.y, w2[4 * k + 1], p1);
                    p2 = fmaf(hv.z, w2[4 * k + 2], p2);
                    p3 = fmaf(hv.w, w2[4 * k + 3], p3);
                }
            } else {
                #pragma unroll
                for (int k = 0; k < 4; k++) {
                    float4 hv = h1v4[12 + k];
                    p0 = fmaf(hv.x, w2[4 * k],     p0);
                    p1 = fmaf(hv.y, w2[4 * k + 1], p1);
                    p2 = fmaf(hv.z, w2[4 * k + 2], p2);
                    p3 = fmaf(hv.w, w2[4 * k + 3], p3);
                }
                #pragma unroll
                for (int k = 0; k < 8; k++) {
                    float4 hv = h2v4[k];
                    p0 = fmaf(hv.x, w2[16 + 4 * k],     p0);
                    p1 = fmaf(hv.y, w2[16 + 4 * k + 1], p1);
                    p2 = fmaf(hv.z, w2[16 + 4 * k + 2], p2);
                    p3 = fmaf(hv.w, w2[16 + 4 * k + 3], p3);
                }
            }
            float part = (p0 + p1) + (p2 + p3);
            float pv = part + __shfl_xor_sync(0xffffffffu, part, 1);
            float gv = (q2 == 2) ? tanh_f(pv) : sigf(pv);
            float vi = __shfl_sync(0xffffffffu, gv, octbase);
            float vf = __shfl_sync(0xffffffffu, gv, octbase + 2);
            float vg = __shfl_sync(0xffffffffu, gv, octbase + 4);
            float vo = __shfl_sync(0xffffffffu, gv, octbase + 6);
            if ((tt & 7) == 0) {
                c2 = vf * c2 + vi * vg;
                float h2v = vo * tanh_f(c2);
                sh2[sp & 1][v] = h2v;
                g_H2[((size_t)sp * 16 + b) * 32 + v] = h2v;
                g_C2[((size_t)sp * 16 + b) * 32 + v] = c2;
            }
            BAR512();
        }
    }
}

// ============== k_f (unchanged) ==============
__global__ __launch_bounds__(256) void k_f(const float* __restrict__ whh1,
                                           const float* __restrict__ wih2,
                                           const float* __restrict__ whh2,
                                           const float* __restrict__ bih2,
                                           const float* __restrict__ bhh2,
                                           const float* __restrict__ fc8w,
                                           const float* __restrict__ fc8b,
                                           float* __restrict__ out_prog,
                                           float* __restrict__ out_fprog) {
    extern __shared__ float smf[];
    float* w1T  = smf;
    float* wi2T = w1T + 64 * 256;
    float* wh2T = wi2T + 64 * 128;
    float* b2s  = wh2T + 32 * 128;
    float* sH1  = b2s + 128;
    float* sC1  = sH1 + 1024;
    float* sH2  = sC1 + 1024;
    float* sC2  = sH2 + 512;
    float* sG1  = sC2 + 512;
    float* sFh1 = sG1 + 4096;
    float* sG2  = sFh1 + 1024;
    float* sFh2 = sG2 + 2048;
    const int t = threadIdx.x;
    const int s = blockIdx.x;
    const size_t r0 = (size_t)s * 16;
    for (int i = t; i < 64 * 256; i += 256) {
        int k = i >> 8, g = i & 255;
        w1T[i] = whh1[g * 64 + k];
    }
    for (int i = t; i < 64 * 128; i += 256) {
        int k = i >> 7, g = i & 127;
        wi2T[i] = wih2[g * 64 + k];
    }
    for (int i = t; i < 32 * 128; i += 256) {
        int k = i >> 7, g = i & 127;
        wh2T[i] = whh2[g * 32 + k];
    }
    if (t < 128) b2s[t] = bih2[t] + bhh2[t];
    for (int i = t; i < 1024; i += 256) sH1[i] = g_H1[r0 * 64 + i];
    for (int i = t; i < 1024; i += 256) sC1[i] = g_C1[r0 * 64 + i];
    for (int i = t; i < 512;  i += 256) sH2[i] = g_H2[r0 * 32 + i];
    for (int i = t; i < 512;  i += 256) sC2[i] = g_C2[r0 * 32 + i];
    for (int i = t; i < 4096; i += 256) sG1[i] = g_X[(size_t)NF * 256 + r0 * 256 + i];
    __syncthreads();
    {
        float acc[16];
        #pragma unroll
        for (int r = 0; r < 16; r++) acc[r] = sG1[r * 256 + t];
        #pragma unroll 8
        for (int k = 0; k < 64; k++) {
            float w = w1T[k * 256 + t];
            #pragma unroll
            for (int r = 0; r < 16; r++) acc[r] = fmaf(sH1[r * 64 + k], w, acc[r]);
        }
        bool is_g = ((t >> 6) == 2);
        #pragma unroll
        for (int r = 0; r < 16; r++)
            sG1[r * 256 + t] = is_g ? tanhf(acc[r]) : sigf(acc[r]);
    }
    __syncthreads();
    for (int i = t; i < 1024; i += 256) {
        int r = i >> 6, u = i & 63;
        const float* g = sG1 + r * 256;
        float c = g[64 + u] * sC1[r * 64 + u] + g[u] * g[128 + u];
        sFh1[r * 64 + u] = g[192 + u] * tanhf(c);
    }
    __syncthreads();
    if (t < 128) {
        float acc[16];
        #pragma unroll
        for (int r = 0; r < 16; r++) acc[r] = b2s[t];
        #pragma unroll 8
        for (int k = 0; k < 64; k++) {
            float w = wi2T[k * 128 + t];
            #pragma unroll
            for (int r = 0; r < 16; r++) acc[r] = fmaf(sFh1[r * 64 + k], w, acc[r]);
        }
        #pragma unroll 8
        for (int k = 0; k < 32; k++) {
            float w = wh2T[k * 128 + t];
            #pragma unroll
            for (int r = 0; r < 16; r++) acc[r] = fmaf(sH2[r * 32 + k], w, acc[r]);
        }
        bool is_g = ((t >> 5) == 2);
        #pragma unroll
        for (int r = 0; r < 16; r++)
            sG2[r * 128 + t] = is_g ? tanhf(acc[r]) : sigf(acc[r]);
    }
    __syncthreads();
    for (int i = t; i < 512; i += 256) {
        int r = i >> 5, u = i & 31;
        const float* g = sG2 + r * 128;
        float c = g[32 + u] * sC2[r * 32 + u] + g[u] * g[64 + u];
        sFh2[r * 32 + u] = g[96 + u] * tanhf(c);
    }
    __syncthreads();
    if (t < 32) {
        int r = t >> 1, which = t & 1;
        const float* v = which ? (sFh2 + r * 32) : (sH2 + r * 32);
        float acc = fc8b[0];
        #pragma unroll
        for (int k = 0; k < 32; k++) acc = fmaf(v[k], fc8w[k], acc);
        float ov = sigf(acc);
        int b = r;
        if (which) out_fprog[(size_t)b * 512 + s] = ov;
        else       out_prog[(size_t)b * 512 + s] = ov;
    }
}

// =====================================================================
extern "C" void kernel_launch(void* const* d_in, const int* in_sizes, int n_in,
                              void* d_out, int out_size) {
    const float* frames  = (const float*)d_in[0];
    const float* spp_w   = (const float*)d_in[1];
    const float* spp_b   = (const float*)d_in[2];
    const float* fore_w  = (const float*)d_in[3];
    const float* fore_b  = (const float*)d_in[4];
    const float* fc7_w   = (const float*)d_in[5];
    const float* fc7_b   = (const float*)d_in[6];
    const float* l1_wih  = (const float*)d_in[7];
    const float* l1_whh  = (const float*)d_in[8];
    const float* l1_bih  = (const float*)d_in[9];
    const float* l1_bhh  = (const float*)d_in[10];
    const float* l2_wih  = (const float*)d_in[11];
    const float* l2_whh  = (const float*)d_in[12];
    const float* l2_bih  = (const float*)d_in[13];
    const float* l2_bhh  = (const float*)d_in[14];
    const float* fc8_w   = (const float*)d_in[15];
    const float* fc8_b   = (const float*)d_in[16];

    float* out         = (float*)d_out;
    float* out_prog    = out;
    float* out_fprog   = out + 8192;
    float* out_pooled  = out + 16384;
    float* out_fpooled = out + 16384 + 737280;

    const int smem_x = (64 * 68 + 64 * 128) * 4;
    const int smem_f = (64 * 256 + 64 * 128 + 32 * 128 + 128 +
                        1024 + 1024 + 512 + 512 + 4096 + 1024 + 2048 + 512) * 4;
    cudaFuncSetAttribute(k_spp, cudaFuncAttributeMaxDynamicSharedMemorySize, SPP_SMEM);
    cudaFuncSetAttribute(k_mlp, cudaFuncAttributeMaxDynamicSharedMemorySize, MLP_SMEM);
    cudaFuncSetAttribute(k_x,   cudaFuncAttributeMaxDynamicSharedMemorySize, smem_x);
    cudaFuncSetAttribute(k_f,   cudaFuncAttributeMaxDynamicSharedMemorySize, smem_f);

    k_spp<<<NF, 256, SPP_SMEM>>>(frames, fore_w, fore_b, out_pooled, out_fpooled);
    k_prepW1<<<EDIM / 8, 256>>>(spp_w);
    k_prepB2<<<64, 256>>>(fc7_w);
    k_mlp<<<128, 512, MLP_SMEM>>>(spp_b, fc7_b);
    k_x<<<dim3(2, 256), 256, smem_x>>>(l1_wih, l1_bih, l1_bhh);
    k_lstm<<<16, 512>>>(l1_whh, l2_wih, l2_whh, l2_bih, l2_bhh);
    k_f<<<512, 256, smem_f>>>(l1_whh, l2_wih, l2_whh, l2_bih, l2_bhh, fc8_w, fc8_b,
                              out_prog, out_fprog);
}